// round 14
// baseline (speedup 1.0000x reference)
#include <cuda_runtime.h>
#include <cuda_bf16.h>
#include <cuda_fp16.h>
#include <cstdint>
#include <math.h>

#define D_MODEL 384
#define N_HEADS 8
#define HEAD_DIM 48
#define BATCH 2
#define NTOK 2048
#define TOTAL_TOK (BATCH * NTOK)
#define QKV_COLS (3 * D_MODEL)

// Scratch (allocation-free)
__device__ __half   g_xh[TOTAL_TOK * D_MODEL];
__device__ __half   g_xl[TOTAL_TOK * D_MODEL];
__device__ uint32_t g_wqt[QKV_COLS * (D_MODEL / 2)];   // [n][kp] half2
__device__ uint32_t g_wot[D_MODEL * (D_MODEL / 2)];
__device__ float    g_qkv[TOTAL_TOK * QKV_COLS];
__device__ __half   g_oh[TOTAL_TOK * D_MODEL];
__device__ __half   g_ol[TOTAL_TOK * D_MODEL];

// ---------------------------------------------------------------------------
// helpers
// ---------------------------------------------------------------------------
__device__ __forceinline__ void mma_f16(float* d, const uint32_t* a, const uint32_t* b) {
    asm volatile(
        "mma.sync.aligned.m16n8k16.row.col.f32.f16.f16.f32 "
        "{%0,%1,%2,%3}, {%4,%5,%6,%7}, {%8,%9}, {%0,%1,%2,%3};"
        : "+f"(d[0]), "+f"(d[1]), "+f"(d[2]), "+f"(d[3])
        : "r"(a[0]), "r"(a[1]), "r"(a[2]), "r"(a[3]), "r"(b[0]), "r"(b[1]));
}

__device__ __forceinline__ uint32_t pack_f16(float x, float y) {
    uint32_t r; asm("cvt.rn.f16x2.f32 %0, %1, %2;" : "=r"(r) : "f"(y), "f"(x)); return r;
}
__device__ __forceinline__ void split_pair_f16(float v0, float v1, uint32_t& hi, uint32_t& lo) {
    hi = pack_f16(v0, v1);
    __half2 h2 = *reinterpret_cast<__half2*>(&hi);
    float2 back = __half22float2(h2);
    lo = pack_f16(v0 - back.x, v1 - back.y);
}

__device__ __forceinline__ float sqrt_approx(float x) {
    float r; asm("sqrt.approx.f32 %0, %1;" : "=f"(r) : "f"(x)); return r;
}
__device__ __forceinline__ float ex2_approx(float x) {
    float r; asm("ex2.approx.f32 %0, %1;" : "=f"(r) : "f"(x)); return r;
}
__device__ __forceinline__ uint32_t smem_u32p(const void* p) {
    uint32_t a;
    asm("{ .reg .u64 t; cvta.to.shared.u64 t, %1; cvt.u32.u64 %0, t; }" : "=r"(a) : "l"(p));
    return a;
}
#define CP_ASYNC16(dst, src) \
    asm volatile("cp.async.cg.shared.global [%0], [%1], 16;" :: "r"(dst), "l"(src) : "memory")
#define CP_COMMIT() asm volatile("cp.async.commit_group;" ::: "memory")
#define CP_WAIT(n)  asm volatile("cp.async.wait_group %0;" :: "n"(n) : "memory")

// ---------------------------------------------------------------------------
// conversion kernels (once per launch)
// ---------------------------------------------------------------------------
__global__ __launch_bounds__(256)
void split_x_kernel(const float* __restrict__ x, __half* __restrict__ xh,
                    __half* __restrict__ xl, int n2)
{
    int i = blockIdx.x * 256 + threadIdx.x;
    if (i >= n2) return;
    float2 v = *reinterpret_cast<const float2*>(x + 2 * (size_t)i);
    uint32_t hi, lo;
    split_pair_f16(v.x, v.y, hi, lo);
    *reinterpret_cast<uint32_t*>(xh + 2 * (size_t)i) = hi;
    *reinterpret_cast<uint32_t*>(xl + 2 * (size_t)i) = lo;
}

__global__ __launch_bounds__(256)
void wtrans_kernel(const float* __restrict__ W, uint32_t* __restrict__ Wt, int N, int K)
{
    int idx = blockIdx.x * 256 + threadIdx.x;
    if (idx >= N * (K / 2)) return;
    int n = idx % N;
    int kp = idx / N;
    float b0 = __ldg(W + (size_t)(2 * kp) * N + n);
    float b1 = __ldg(W + (size_t)(2 * kp + 1) * N + n);
    Wt[(size_t)n * (K / 2) + kp] = pack_f16(b0, b1);
}

// ---------------------------------------------------------------------------
// FP16 GEMM, cp.async double-buffered; columns >= two_term_from get the
// Al residual term (2-term, x exact), others single-term.
// C = (Ah [+ Al]) @ Bt + bias. BM=128, BN=64, BK=32; 256 threads.
// ---------------------------------------------------------------------------
#define GBM 128
#define GBN 64
#define GBK 32
#define ASTR 20
#define BSTR 20
#define A_TILE_U32 (GBM * ASTR)     // 2560
#define B_TILE_U32 (GBN * BSTR)     // 1280
#define SMEM_GEMM ((2 * A_TILE_U32 * 2 + 2 * B_TILE_U32) * 4)   // 51200 B

template <typename OutT>
__global__ __launch_bounds__(256)
void gemm_h_kernel(const __half* __restrict__ Ah, const __half* __restrict__ Al,
                   const uint32_t* __restrict__ Bt, const float* __restrict__ bias,
                   OutT* __restrict__ C, int M, int N, int K, int two_term_from)
{
    extern __shared__ uint32_t smem[];
    uint32_t* sAh = smem;
    uint32_t* sAl = smem + 2 * A_TILE_U32;
    uint32_t* sBh = smem + 4 * A_TILE_U32;

    const int tid = threadIdx.x;
    const int w = tid >> 5;
    const int lane = tid & 31;
    const int g = lane >> 2;
    const int t = lane & 3;
    const int wm = w >> 1;
    const int wn = w & 1;
    const int row0 = blockIdx.y * GBM;
    const int col0 = blockIdx.x * GBN;
    const int Kp = K / 2;
    const int NT = K / GBK;
    const bool two_term = (col0 >= two_term_from);

    const int a_r0 = (tid + 0)   >> 2, a_q0 = (tid + 0)   & 3;
    const int a_r1 = (tid + 256) >> 2, a_q1 = (tid + 256) & 3;
    const int b_n = tid >> 2, b_q = tid & 3;

    auto stage = [&](int k0, int buf) {
        uint32_t d;
        d = smem_u32p(&sAh[buf * A_TILE_U32 + a_r0 * ASTR + 4 * a_q0]);
        CP_ASYNC16(d, Ah + (size_t)(row0 + a_r0) * K + k0 + 8 * a_q0);
        d = smem_u32p(&sAh[buf * A_TILE_U32 + a_r1 * ASTR + 4 * a_q1]);
        CP_ASYNC16(d, Ah + (size_t)(row0 + a_r1) * K + k0 + 8 * a_q1);
        if (two_term) {
            d = smem_u32p(&sAl[buf * A_TILE_U32 + a_r0 * ASTR + 4 * a_q0]);
            CP_ASYNC16(d, Al + (size_t)(row0 + a_r0) * K + k0 + 8 * a_q0);
            d = smem_u32p(&sAl[buf * A_TILE_U32 + a_r1 * ASTR + 4 * a_q1]);
            CP_ASYNC16(d, Al + (size_t)(row0 + a_r1) * K + k0 + 8 * a_q1);
        }
        d = smem_u32p(&sBh[buf * B_TILE_U32 + b_n * BSTR + 4 * b_q]);
        CP_ASYNC16(d, Bt + (size_t)(col0 + b_n) * Kp + (k0 >> 1) + 4 * b_q);
        CP_COMMIT();
    };

    float acc[2][4][4];
    #pragma unroll
    for (int mt = 0; mt < 2; mt++)
        #pragma unroll
        for (int nb = 0; nb < 4; nb++)
            #pragma unroll
            for (int e = 0; e < 4; e++) acc[mt][nb][e] = 0.f;

    stage(0, 0);

    for (int kt = 0; kt < NT; kt++) {
        const int buf = kt & 1;
        if (kt + 1 < NT) {
            stage((kt + 1) * GBK, (kt + 1) & 1);
            CP_WAIT(1);
        } else {
            CP_WAIT(0);
        }
        __syncthreads();

        const uint32_t* cAh = sAh + buf * A_TILE_U32;
        const uint32_t* cAl = sAl + buf * A_TILE_U32;
        const uint32_t* cBh = sBh + buf * B_TILE_U32;

        #pragma unroll
        for (int kc = 0; kc < 2; kc++) {
            uint32_t ah[2][4], al[2][4];
            #pragma unroll
            for (int mt = 0; mt < 2; mt++) {
                const int rA = (32 * wm + 16 * mt + g) * ASTR + 8 * kc;
                const int rB = rA + 8 * ASTR;
                ah[mt][0] = cAh[rA + t];
                ah[mt][1] = cAh[rB + t];
                ah[mt][2] = cAh[rA + t + 4];
                ah[mt][3] = cAh[rB + t + 4];
                if (two_term) {
                    al[mt][0] = cAl[rA + t];
                    al[mt][1] = cAl[rB + t];
                    al[mt][2] = cAl[rA + t + 4];
                    al[mt][3] = cAl[rB + t + 4];
                }
            }
            #pragma unroll
            for (int nb = 0; nb < 4; nb++) {
                const int nbase = (32 * wn + 8 * nb + g) * BSTR + 8 * kc;
                uint32_t bh_[2];
                bh_[0] = cBh[nbase + t];
                bh_[1] = cBh[nbase + t + 4];
                mma_f16(acc[0][nb], ah[0], bh_);
                mma_f16(acc[1][nb], ah[1], bh_);
                if (two_term) {
                    mma_f16(acc[0][nb], al[0], bh_);
                    mma_f16(acc[1][nb], al[1], bh_);
                }
            }
        }
        __syncthreads();
    }

    #pragma unroll
    for (int mt = 0; mt < 2; mt++) {
        const int rA = row0 + 32 * wm + 16 * mt + g;
        #pragma unroll
        for (int nb = 0; nb < 4; nb++) {
            const int c = col0 + 32 * wn + 8 * nb + 2 * t;
            const float bx = bias[c], by = bias[c + 1];
            if constexpr (sizeof(OutT) == 4) {
                *reinterpret_cast<float2*>((float*)C + (size_t)rA * N + c) =
                    make_float2(acc[mt][nb][0] + bx, acc[mt][nb][1] + by);
                *reinterpret_cast<float2*>((float*)C + (size_t)(rA + 8) * N + c) =
                    make_float2(acc[mt][nb][2] + bx, acc[mt][nb][3] + by);
            } else {
                *reinterpret_cast<uint32_t*>((__half*)C + (size_t)rA * N + c) =
                    pack_f16(acc[mt][nb][0] + bx, acc[mt][nb][1] + by);
                *reinterpret_cast<uint32_t*>((__half*)C + (size_t)(rA + 8) * N + c) =
                    pack_f16(acc[mt][nb][2] + bx, acc[mt][nb][3] + by);
            }
        }
    }
}

// ---------------------------------------------------------------------------
// Fused attention — R10 kernel (measured best), fp32 qkv input, pack-to-fp16
// staging; epilogue writes hi/lo split halves for the out-projection.
// ---------------------------------------------------------------------------
#define TJ 64
#define MQ 256
#define N_ITERS (NTOK / TJ)
#define KSTR 28
#define VSTR 36
#define LOG2E 1.4426950408889634f

__global__ __launch_bounds__(256, 1)
void attn_mma_kernel(const float* __restrict__ qkv, const float* __restrict__ coords,
                     const float* __restrict__ W_dist,
                     __half* __restrict__ oh, __half* __restrict__ ol)
{
    __shared__ uint32_t sKh[TJ * KSTR];
    __shared__ uint32_t sVh[HEAD_DIM * VSTR];
    __shared__ float sC[3][TJ];

    const int tid = threadIdx.x;
    const int w = tid >> 5;
    const int lane = tid & 31;
    const int g = lane >> 2;
    const int t = lane & 3;
    const int bh = blockIdx.y;
    const int b = bh >> 3, h = bh & 7;
    const int q0 = blockIdx.x * MQ;

    const float qscale = 0.14433756729740643f * LOG2E;
    const float wd2 = __ldg(W_dist + h) * LOG2E;

    const float* gKbase = qkv + (size_t)(b * NTOK) * QKV_COLS + D_MODEL + h * HEAD_DIM;
    const float* gVbase = gKbase + D_MODEL;

    float4 pK[3];
    float2 pV[6];
    float pC = 0.f;

    // ---- initial prefetch (tile 0) ----
    #pragma unroll
    for (int ii = 0; ii < 3; ii++) {
        const int idx = tid + 256 * ii;
        const int r = idx / 12, c4 = (idx % 12) * 4;
        pK[ii] = __ldg(reinterpret_cast<const float4*>(gKbase + (size_t)r * QKV_COLS + c4));
    }
    #pragma unroll
    for (int ii = 0; ii < 3; ii++) {
        const int p = tid + 256 * ii;
        const int kp = p / 24, dp = p % 24;
        pV[2 * ii].x     = __ldg(gVbase + (size_t)(2 * kp) * QKV_COLS + 2 * dp);
        pV[2 * ii].y     = __ldg(gVbase + (size_t)(2 * kp) * QKV_COLS + 2 * dp + 1);
        pV[2 * ii + 1].x = __ldg(gVbase + (size_t)(2 * kp + 1) * QKV_COLS + 2 * dp);
        pV[2 * ii + 1].y = __ldg(gVbase + (size_t)(2 * kp + 1) * QKV_COLS + 2 * dp + 1);
    }
    if (tid < 192) {
        pC = __ldg(coords + (size_t)(b * NTOK + tid / 3) * 3 + (tid % 3));
    }

    // ---- Q fragments, single fp16 (pre-scaled) ----
    uint32_t qh[2][3][4];
    {
        const float* gQ = qkv + (size_t)(b * NTOK + q0) * QKV_COLS + h * HEAD_DIM;
        #pragma unroll
        for (int mt = 0; mt < 2; mt++) {
            const int rA = 32 * w + 16 * mt + g;
            #pragma unroll
            for (int kb = 0; kb < 3; kb++) {
                const int c = 16 * kb + 2 * t;
                float2 v0 = __ldg(reinterpret_cast<const float2*>(gQ + (size_t)rA * QKV_COLS + c));
                float2 v1 = __ldg(reinterpret_cast<const float2*>(gQ + (size_t)(rA + 8) * QKV_COLS + c));
                float2 v2 = __ldg(reinterpret_cast<const float2*>(gQ + (size_t)rA * QKV_COLS + c + 8));
                float2 v3 = __ldg(reinterpret_cast<const float2*>(gQ + (size_t)(rA + 8) * QKV_COLS + c + 8));
                qh[mt][kb][0] = pack_f16(v0.x * qscale, v0.y * qscale);
                qh[mt][kb][1] = pack_f16(v1.x * qscale, v1.y * qscale);
                qh[mt][kb][2] = pack_f16(v2.x * qscale, v2.y * qscale);
                qh[mt][kb][3] = pack_f16(v3.x * qscale, v3.y * qscale);
            }
        }
    }

    float qcx[4], qcy[4], qcz[4];
    #pragma unroll
    for (int rr = 0; rr < 4; rr++) {
        const int row = 32 * w + 8 * rr + g;
        const float* cp = coords + (size_t)(b * NTOK + q0 + row) * 3;
        qcx[rr] = __ldg(cp + 0); qcy[rr] = __ldg(cp + 1); qcz[rr] = __ldg(cp + 2);
    }

    float o[2][6][4];
    #pragma unroll
    for (int mt = 0; mt < 2; mt++)
        #pragma unroll
        for (int nb = 0; nb < 6; nb++)
            #pragma unroll
            for (int e = 0; e < 4; e++) o[mt][nb][e] = 0.f;

    float lsum[4] = {0.f, 0.f, 0.f, 0.f};

    for (int it = 0; it < N_ITERS; ++it) {
        __syncthreads();

        // ---- STS: pack prefetched tile to fp16 smem ----
        #pragma unroll
        for (int ii = 0; ii < 3; ii++) {
            const int idx = tid + 256 * ii;
            const int r = idx / 12, c4 = (idx % 12) * 4;
            const int kwi = r * KSTR + (c4 >> 1);
            sKh[kwi] = pack_f16(pK[ii].x, pK[ii].y);
            sKh[kwi + 1] = pack_f16(pK[ii].z, pK[ii].w);
        }
        #pragma unroll
        for (int ii = 0; ii < 3; ii++) {
            const int p = tid + 256 * ii;
            const int kp = p / 24, dp = p % 24;
            const int d = 2 * dp;
            sVh[d * VSTR + kp]       = pack_f16(pV[2 * ii].x, pV[2 * ii + 1].x);
            sVh[(d + 1) * VSTR + kp] = pack_f16(pV[2 * ii].y, pV[2 * ii + 1].y);
        }
        if (tid < 192) sC[tid % 3][tid / 3] = pC;
        __syncthreads();

        // ---- prefetch next tile ----
        if (it + 1 < N_ITERS) {
            const int j1 = (it + 1) * TJ;
            #pragma unroll
            for (int ii = 0; ii < 3; ii++) {
                const int idx = tid + 256 * ii;
                const int r = idx / 12, c4 = (idx % 12) * 4;
                pK[ii] = __ldg(reinterpret_cast<const float4*>(gKbase + (size_t)(j1 + r) * QKV_COLS + c4));
            }
            #pragma unroll
            for (int ii = 0; ii < 3; ii++) {
                const int p = tid + 256 * ii;
                const int kp = p / 24, dp = p % 24;
                pV[2 * ii].x     = __ldg(gVbase + (size_t)(j1 + 2 * kp) * QKV_COLS + 2 * dp);
                pV[2 * ii].y     = __ldg(gVbase + (size_t)(j1 + 2 * kp) * QKV_COLS + 2 * dp + 1);
                pV[2 * ii + 1].x = __ldg(gVbase + (size_t)(j1 + 2 * kp + 1) * QKV_COLS + 2 * dp);
                pV[2 * ii + 1].y = __ldg(gVbase + (size_t)(j1 + 2 * kp + 1) * QKV_COLS + 2 * dp + 1);
            }
            if (tid < 192) {
                pC = __ldg(coords + (size_t)(b * NTOK + j1 + tid / 3) * 3 + (tid % 3));
            }
        }

        // ---- S = q @ k^T (single fp16) ----
        float s[2][8][4];
        #pragma unroll
        for (int mt = 0; mt < 2; mt++)
            #pragma unroll
            for (int nb = 0; nb < 8; nb++)
                #pragma unroll
                for (int e = 0; e < 4; e++) s[mt][nb][e] = 0.f;

        #pragma unroll
        for (int kb = 0; kb < 3; kb++) {
            #pragma unroll
            for (int nbp = 0; nbp < 4; nbp++) {
                const int nb0 = 2 * nbp, nb1 = 2 * nbp + 1;
                const int kb0 = (8 * nb0 + g) * KSTR + 8 * kb;
                const int kb1 = (8 * nb1 + g) * KSTR + 8 * kb;
                uint32_t b0h[2], b1h[2];
                b0h[0] = sKh[kb0 + t]; b0h[1] = sKh[kb0 + t + 4];
                b1h[0] = sKh[kb1 + t]; b1h[1] = sKh[kb1 + t + 4];
                mma_f16(s[0][nb0], qh[0][kb], b0h);
                mma_f16(s[0][nb1], qh[0][kb], b1h);
                mma_f16(s[1][nb0], qh[1][kb], b0h);
                mma_f16(s[1][nb1], qh[1][kb], b1h);
            }
        }

        // ---- per key-chunk: softmax interleaved with PV ----
        #pragma unroll
        for (int kb = 0; kb < 4; kb++) {
            #pragma unroll
            for (int nbo = 0; nbo < 2; nbo++) {
                const int nb = 2 * kb + nbo;
                const int c0 = 8 * nb + 2 * t;
                const float kx0 = sC[0][c0], ky0 = sC[1][c0], kz0 = sC[2][c0];
                const float kx1 = sC[0][c0 + 1], ky1 = sC[1][c0 + 1], kz1 = sC[2][c0 + 1];
                #pragma unroll
                for (int mt = 0; mt < 2; mt++) {
                    #pragma unroll
                    for (int half = 0; half < 2; half++) {
                        const int rr = 2 * mt + half;
                        float dx0 = qcx[rr] - kx0, dy0 = qcy[rr] - ky0, dz0 = qcz[rr] - kz0;
                        float dx1 = qcx[rr] - kx1, dy1 = qcy[rr] - ky1, dz1 = qcz[rr] - kz1;
                        float d0 = sqrt_approx(fmaf(dx0, dx0, fmaf(dy0, dy0, dz0 * dz0)));
                        float d1 = sqrt_approx(fmaf(dx1, dx1, fmaf(dy1, dy1, dz1 * dz1)));
                        float p0 = ex2_approx(fmaf(wd2, d0, s[mt][nb][2 * half]));
                        float p1 = ex2_approx(fmaf(wd2, d1, s[mt][nb][2 * half + 1]));
                        s[mt][nb][2 * half] = p0;
                        s[mt][nb][2 * half + 1] = p1;
                        lsum[rr] += p0 + p1;
                    }
                }
            }
            // pack P into fp16 A-fragments
            uint32_t ah[2][4];
            #pragma unroll
            for (int mt = 0; mt < 2; mt++) {
                ah[mt][0] = pack_f16(s[mt][2 * kb][0],     s[mt][2 * kb][1]);
                ah[mt][1] = pack_f16(s[mt][2 * kb][2],     s[mt][2 * kb][3]);
                ah[mt][2] = pack_f16(s[mt][2 * kb + 1][0], s[mt][2 * kb + 1][1]);
                ah[mt][3] = pack_f16(s[mt][2 * kb + 1][2], s[mt][2 * kb + 1][3]);
            }
            // O += p @ v
            #pragma unroll
            for (int nbp = 0; nbp < 3; nbp++) {
                const int nb0 = 2 * nbp, nb1 = 2 * nbp + 1;
                const int vb0 = (8 * nb0 + g) * VSTR + 8 * kb;
                const int vb1 = (8 * nb1 + g) * VSTR + 8 * kb;
                uint32_t v0h[2], v1h[2];
                v0h[0] = sVh[vb0 + t]; v0h[1] = sVh[vb0 + t + 4];
                v1h[0] = sVh[vb1 + t]; v1h[1] = sVh[vb1 + t + 4];
                mma_f16(o[0][nb0], ah[0], v0h);
                mma_f16(o[0][nb1], ah[0], v1h);
                mma_f16(o[1][nb0], ah[1], v0h);
                mma_f16(o[1][nb1], ah[1], v1h);
            }
        }
    }

    // ---- finalize: reduce row sums, write hi/lo split halves ----
    #pragma unroll
    for (int rr = 0; rr < 4; rr++) {
        lsum[rr] += __shfl_xor_sync(0xffffffffu, lsum[rr], 1);
        lsum[rr] += __shfl_xor_sync(0xffffffffu, lsum[rr], 2);
        lsum[rr] = 1.f / lsum[rr];
    }

    #pragma unroll
    for (int mt = 0; mt < 2; mt++) {
        const int rowA = 32 * w + 16 * mt + g;
        const size_t baseA = (size_t)(b * NTOK + q0 + rowA) * D_MODEL + h * HEAD_DIM;
        const size_t baseB = baseA + (size_t)8 * D_MODEL;
        const float invA = lsum[2 * mt], invB = lsum[2 * mt + 1];
        #pragma unroll
        for (int nb = 0; nb < 6; nb++) {
            const int c = 8 * nb + 2 * t;
            uint32_t hiA, loA, hiB, loB;
            split_pair_f16(o[mt][nb][0] * invA, o[mt][nb][1] * invA, hiA, loA);
            split_pair_f16(o[mt][nb][2] * invB, o[mt][nb][3] * invB, hiB, loB);
            *reinterpret_cast<uint32_t*>(oh + baseA + c) = hiA;
            *reinterpret_cast<uint32_t*>(ol + baseA + c) = loA;
            *reinterpret_cast<uint32_t*>(oh + baseB + c) = hiB;
            *reinterpret_cast<uint32_t*>(ol + baseB + c) = loB;
        }
    }
}

// ---------------------------------------------------------------------------
extern "C" void kernel_launch(void* const* d_in, const int* in_sizes, int n_in,
                              void* d_out, int out_size)
{
    const float* x      = (const float*)d_in[0];
    const float* coords = (const float*)d_in[1];
    const float* W_qkv  = (const float*)d_in[2];
    const float* b_qkv  = (const float*)d_in[3];
    const float* W_dist = (const float*)d_in[4];
    const float* W_out  = (const float*)d_in[6];
    const float* b_out  = (const float*)d_in[7];
    float* out = (float*)d_out;

    __half *xh, *xl, *oh, *ol;
    float* qkvf;
    uint32_t *wqt, *wot;
    cudaGetSymbolAddress((void**)&xh, g_xh);
    cudaGetSymbolAddress((void**)&xl, g_xl);
    cudaGetSymbolAddress((void**)&wqt, g_wqt);
    cudaGetSymbolAddress((void**)&wot, g_wot);
    cudaGetSymbolAddress((void**)&qkvf, g_qkv);
    cudaGetSymbolAddress((void**)&oh, g_oh);
    cudaGetSymbolAddress((void**)&ol, g_ol);

    cudaFuncSetAttribute(gemm_h_kernel<float>,
                         cudaFuncAttributeMaxDynamicSharedMemorySize, SMEM_GEMM);

    // 0) conversions
    split_x_kernel<<<(TOTAL_TOK * D_MODEL / 2 + 255) / 256, 256>>>(x, xh, xl, TOTAL_TOK * D_MODEL / 2);
    wtrans_kernel<<<(QKV_COLS * (D_MODEL / 2) + 255) / 256, 256>>>(W_qkv, wqt, QKV_COLS, D_MODEL);
    wtrans_kernel<<<(D_MODEL * (D_MODEL / 2) + 255) / 256, 256>>>(W_out, wot, D_MODEL, D_MODEL);

    // 1) QKV projection -> fp32; q,k cols single-term, v cols 2-term
    {
        dim3 grid(QKV_COLS / GBN, TOTAL_TOK / GBM);
        gemm_h_kernel<float><<<grid, 256, SMEM_GEMM>>>(xh, xl, wqt, b_qkv, qkvf,
                                                       TOTAL_TOK, QKV_COLS, D_MODEL,
                                                       2 * D_MODEL);
    }

    // 2) fused attention -> split fp16 (R10 kernel + split epilogue)
    {
        dim3 grid(NTOK / MQ, BATCH * N_HEADS);
        attn_mma_kernel<<<grid, 256>>>(qkvf, coords, W_dist, oh, ol);
    }

    // 3) Output projection (all 2-term) -> fp32
    {
        dim3 grid(D_MODEL / GBN, TOTAL_TOK / GBM);
        gemm_h_kernel<float><<<grid, 256, SMEM_GEMM>>>(oh, ol, wot, b_out, out,
                                                       TOTAL_TOK, D_MODEL, D_MODEL, 0);
    }
}

// round 15
// speedup vs baseline: 1.0014x; 1.0014x over previous
#include <cuda_runtime.h>
#include <cuda_bf16.h>
#include <cuda_fp16.h>
#include <cstdint>
#include <math.h>

#define D_MODEL 384
#define N_HEADS 8
#define HEAD_DIM 48
#define BATCH 2
#define NTOK 2048
#define TOTAL_TOK (BATCH * NTOK)
#define QKV_COLS (3 * D_MODEL)

// Scratch (allocation-free)
__device__ __half   g_xh[TOTAL_TOK * D_MODEL];
__device__ __half   g_xl[TOTAL_TOK * D_MODEL];
__device__ uint32_t g_wqt[QKV_COLS * (D_MODEL / 2)];   // [n][kp] half2
__device__ uint32_t g_wot[D_MODEL * (D_MODEL / 2)];
__device__ float    g_qkv[TOTAL_TOK * QKV_COLS];
__device__ float    g_attn[TOTAL_TOK * D_MODEL];
__device__ __half   g_oh[TOTAL_TOK * D_MODEL];
__device__ __half   g_ol[TOTAL_TOK * D_MODEL];

// ---------------------------------------------------------------------------
// helpers
// ---------------------------------------------------------------------------
__device__ __forceinline__ void mma_f16(float* d, const uint32_t* a, const uint32_t* b) {
    asm volatile(
        "mma.sync.aligned.m16n8k16.row.col.f32.f16.f16.f32 "
        "{%0,%1,%2,%3}, {%4,%5,%6,%7}, {%8,%9}, {%0,%1,%2,%3};"
        : "+f"(d[0]), "+f"(d[1]), "+f"(d[2]), "+f"(d[3])
        : "r"(a[0]), "r"(a[1]), "r"(a[2]), "r"(a[3]), "r"(b[0]), "r"(b[1]));
}

__device__ __forceinline__ uint32_t pack_f16(float x, float y) {
    uint32_t r; asm("cvt.rn.f16x2.f32 %0, %1, %2;" : "=r"(r) : "f"(y), "f"(x)); return r;
}
__device__ __forceinline__ void split_pair_f16(float v0, float v1, uint32_t& hi, uint32_t& lo) {
    hi = pack_f16(v0, v1);
    __half2 h2 = *reinterpret_cast<__half2*>(&hi);
    float2 back = __half22float2(h2);
    lo = pack_f16(v0 - back.x, v1 - back.y);
}

__device__ __forceinline__ float sqrt_approx(float x) {
    float r; asm("sqrt.approx.f32 %0, %1;" : "=f"(r) : "f"(x)); return r;
}
__device__ __forceinline__ float ex2_approx(float x) {
    float r; asm("ex2.approx.f32 %0, %1;" : "=f"(r) : "f"(x)); return r;
}
__device__ __forceinline__ uint32_t smem_u32p(const void* p) {
    uint32_t a;
    asm("{ .reg .u64 t; cvta.to.shared.u64 t, %1; cvt.u32.u64 %0, t; }" : "=r"(a) : "l"(p));
    return a;
}
#define CP_ASYNC16(dst, src) \
    asm volatile("cp.async.cg.shared.global [%0], [%1], 16;" :: "r"(dst), "l"(src) : "memory")
#define CP_COMMIT() asm volatile("cp.async.commit_group;" ::: "memory")
#define CP_WAIT(n)  asm volatile("cp.async.wait_group %0;" :: "n"(n) : "memory")

// ---------------------------------------------------------------------------
// conversion kernels
// ---------------------------------------------------------------------------
__global__ __launch_bounds__(256)
void split_x_kernel(const float* __restrict__ x, __half* __restrict__ xh,
                    __half* __restrict__ xl, int n2)
{
    int i = blockIdx.x * 256 + threadIdx.x;
    if (i >= n2) return;
    float2 v = *reinterpret_cast<const float2*>(x + 2 * (size_t)i);
    uint32_t hi, lo;
    split_pair_f16(v.x, v.y, hi, lo);
    *reinterpret_cast<uint32_t*>(xh + 2 * (size_t)i) = hi;
    *reinterpret_cast<uint32_t*>(xl + 2 * (size_t)i) = lo;
}

__global__ __launch_bounds__(256)
void wtrans_kernel(const float* __restrict__ W, uint32_t* __restrict__ Wt, int N, int K)
{
    int idx = blockIdx.x * 256 + threadIdx.x;
    if (idx >= N * (K / 2)) return;
    int n = idx % N;
    int kp = idx / N;
    float b0 = __ldg(W + (size_t)(2 * kp) * N + n);
    float b1 = __ldg(W + (size_t)(2 * kp + 1) * N + n);
    Wt[(size_t)n * (K / 2) + kp] = pack_f16(b0, b1);
}

// ---------------------------------------------------------------------------
// FP16 GEMM, cp.async double-buffered; columns >= two_term_from get Al term.
// ---------------------------------------------------------------------------
#define GBM 128
#define GBN 64
#define GBK 32
#define ASTR 20
#define BSTR 20
#define A_TILE_U32 (GBM * ASTR)
#define B_TILE_U32 (GBN * BSTR)
#define SMEM_GEMM ((2 * A_TILE_U32 * 2 + 2 * B_TILE_U32) * 4)

__global__ __launch_bounds__(256)
void gemm_h_kernel(const __half* __restrict__ Ah, const __half* __restrict__ Al,
                   const uint32_t* __restrict__ Bt, const float* __restrict__ bias,
                   float* __restrict__ C, int M, int N, int K, int two_term_from)
{
    extern __shared__ uint32_t smem[];
    uint32_t* sAh = smem;
    uint32_t* sAl = smem + 2 * A_TILE_U32;
    uint32_t* sBh = smem + 4 * A_TILE_U32;

    const int tid = threadIdx.x;
    const int w = tid >> 5;
    const int lane = tid & 31;
    const int g = lane >> 2;
    const int t = lane & 3;
    const int wm = w >> 1;
    const int wn = w & 1;
    const int row0 = blockIdx.y * GBM;
    const int col0 = blockIdx.x * GBN;
    const int Kp = K / 2;
    const int NT = K / GBK;
    const bool two_term = (col0 >= two_term_from);

    const int a_r0 = (tid + 0)   >> 2, a_q0 = (tid + 0)   & 3;
    const int a_r1 = (tid + 256) >> 2, a_q1 = (tid + 256) & 3;
    const int b_n = tid >> 2, b_q = tid & 3;

    auto stage = [&](int k0, int buf) {
        uint32_t d;
        d = smem_u32p(&sAh[buf * A_TILE_U32 + a_r0 * ASTR + 4 * a_q0]);
        CP_ASYNC16(d, Ah + (size_t)(row0 + a_r0) * K + k0 + 8 * a_q0);
        d = smem_u32p(&sAh[buf * A_TILE_U32 + a_r1 * ASTR + 4 * a_q1]);
        CP_ASYNC16(d, Ah + (size_t)(row0 + a_r1) * K + k0 + 8 * a_q1);
        if (two_term) {
            d = smem_u32p(&sAl[buf * A_TILE_U32 + a_r0 * ASTR + 4 * a_q0]);
            CP_ASYNC16(d, Al + (size_t)(row0 + a_r0) * K + k0 + 8 * a_q0);
            d = smem_u32p(&sAl[buf * A_TILE_U32 + a_r1 * ASTR + 4 * a_q1]);
            CP_ASYNC16(d, Al + (size_t)(row0 + a_r1) * K + k0 + 8 * a_q1);
        }
        d = smem_u32p(&sBh[buf * B_TILE_U32 + b_n * BSTR + 4 * b_q]);
        CP_ASYNC16(d, Bt + (size_t)(col0 + b_n) * Kp + (k0 >> 1) + 4 * b_q);
        CP_COMMIT();
    };

    float acc[2][4][4];
    #pragma unroll
    for (int mt = 0; mt < 2; mt++)
        #pragma unroll
        for (int nb = 0; nb < 4; nb++)
            #pragma unroll
            for (int e = 0; e < 4; e++) acc[mt][nb][e] = 0.f;

    stage(0, 0);

    for (int kt = 0; kt < NT; kt++) {
        const int buf = kt & 1;
        if (kt + 1 < NT) {
            stage((kt + 1) * GBK, (kt + 1) & 1);
            CP_WAIT(1);
        } else {
            CP_WAIT(0);
        }
        __syncthreads();

        const uint32_t* cAh = sAh + buf * A_TILE_U32;
        const uint32_t* cAl = sAl + buf * A_TILE_U32;
        const uint32_t* cBh = sBh + buf * B_TILE_U32;

        #pragma unroll
        for (int kc = 0; kc < 2; kc++) {
            uint32_t ah[2][4], al[2][4];
            #pragma unroll
            for (int mt = 0; mt < 2; mt++) {
                const int rA = (32 * wm + 16 * mt + g) * ASTR + 8 * kc;
                const int rB = rA + 8 * ASTR;
                ah[mt][0] = cAh[rA + t];
                ah[mt][1] = cAh[rB + t];
                ah[mt][2] = cAh[rA + t + 4];
                ah[mt][3] = cAh[rB + t + 4];
                if (two_term) {
                    al[mt][0] = cAl[rA + t];
                    al[mt][1] = cAl[rB + t];
                    al[mt][2] = cAl[rA + t + 4];
                    al[mt][3] = cAl[rB + t + 4];
                }
            }
            #pragma unroll
            for (int nb = 0; nb < 4; nb++) {
                const int nbase = (32 * wn + 8 * nb + g) * BSTR + 8 * kc;
                uint32_t bh_[2];
                bh_[0] = cBh[nbase + t];
                bh_[1] = cBh[nbase + t + 4];
                mma_f16(acc[0][nb], ah[0], bh_);
                mma_f16(acc[1][nb], ah[1], bh_);
                if (two_term) {
                    mma_f16(acc[0][nb], al[0], bh_);
                    mma_f16(acc[1][nb], al[1], bh_);
                }
            }
        }
        __syncthreads();
    }

    #pragma unroll
    for (int mt = 0; mt < 2; mt++) {
        const int rA = row0 + 32 * wm + 16 * mt + g;
        #pragma unroll
        for (int nb = 0; nb < 4; nb++) {
            const int c = col0 + 32 * wn + 8 * nb + 2 * t;
            const float bx = bias[c], by = bias[c + 1];
            *reinterpret_cast<float2*>(C + (size_t)rA * N + c) =
                make_float2(acc[mt][nb][0] + bx, acc[mt][nb][1] + by);
            *reinterpret_cast<float2*>(C + (size_t)(rA + 8) * N + c) =
                make_float2(acc[mt][nb][2] + bx, acc[mt][nb][3] + by);
        }
    }
}

// ---------------------------------------------------------------------------
// Fused attention — R10 kernel, byte-identical (fp32 qkv in, fp32 out).
// ---------------------------------------------------------------------------
#define TJ 64
#define MQ 256
#define N_ITERS (NTOK / TJ)
#define KSTR 28
#define VSTR 36
#define LOG2E 1.4426950408889634f

__global__ __launch_bounds__(256, 1)
void attn_mma_kernel(const float* __restrict__ qkv, const float* __restrict__ coords,
                     const float* __restrict__ W_dist,
                     float* __restrict__ out)
{
    __shared__ uint32_t sKh[TJ * KSTR];
    __shared__ uint32_t sVh[HEAD_DIM * VSTR];
    __shared__ float sC[3][TJ];

    const int tid = threadIdx.x;
    const int w = tid >> 5;
    const int lane = tid & 31;
    const int g = lane >> 2;
    const int t = lane & 3;
    const int bh = blockIdx.y;
    const int b = bh >> 3, h = bh & 7;
    const int q0 = blockIdx.x * MQ;

    const float qscale = 0.14433756729740643f * LOG2E;
    const float wd2 = __ldg(W_dist + h) * LOG2E;

    const float* gKbase = qkv + (size_t)(b * NTOK) * QKV_COLS + D_MODEL + h * HEAD_DIM;
    const float* gVbase = gKbase + D_MODEL;

    float4 pK[3];
    float2 pV[6];
    float pC = 0.f;

    #pragma unroll
    for (int ii = 0; ii < 3; ii++) {
        const int idx = tid + 256 * ii;
        const int r = idx / 12, c4 = (idx % 12) * 4;
        pK[ii] = __ldg(reinterpret_cast<const float4*>(gKbase + (size_t)r * QKV_COLS + c4));
    }
    #pragma unroll
    for (int ii = 0; ii < 3; ii++) {
        const int p = tid + 256 * ii;
        const int kp = p / 24, dp = p % 24;
        pV[2 * ii]     = __ldg(reinterpret_cast<const float2*>(gVbase + (size_t)(2 * kp) * QKV_COLS + 2 * dp));
        pV[2 * ii + 1] = __ldg(reinterpret_cast<const float2*>(gVbase + (size_t)(2 * kp + 1) * QKV_COLS + 2 * dp));
    }
    if (tid < 192) {
        pC = __ldg(coords + (size_t)(b * NTOK + tid / 3) * 3 + (tid % 3));
    }

    uint32_t qh[2][3][4];
    {
        const float* gQ = qkv + (size_t)(b * NTOK + q0) * QKV_COLS + h * HEAD_DIM;
        #pragma unroll
        for (int mt = 0; mt < 2; mt++) {
            const int rA = 32 * w + 16 * mt + g;
            #pragma unroll
            for (int kb = 0; kb < 3; kb++) {
                const int c = 16 * kb + 2 * t;
                float2 v0 = __ldg(reinterpret_cast<const float2*>(gQ + (size_t)rA * QKV_COLS + c));
                float2 v1 = __ldg(reinterpret_cast<const float2*>(gQ + (size_t)(rA + 8) * QKV_COLS + c));
                float2 v2 = __ldg(reinterpret_cast<const float2*>(gQ + (size_t)rA * QKV_COLS + c + 8));
                float2 v3 = __ldg(reinterpret_cast<const float2*>(gQ + (size_t)(rA + 8) * QKV_COLS + c + 8));
                qh[mt][kb][0] = pack_f16(v0.x * qscale, v0.y * qscale);
                qh[mt][kb][1] = pack_f16(v1.x * qscale, v1.y * qscale);
                qh[mt][kb][2] = pack_f16(v2.x * qscale, v2.y * qscale);
                qh[mt][kb][3] = pack_f16(v3.x * qscale, v3.y * qscale);
            }
        }
    }

    float qcx[4], qcy[4], qcz[4];
    #pragma unroll
    for (int rr = 0; rr < 4; rr++) {
        const int row = 32 * w + 8 * rr + g;
        const float* cp = coords + (size_t)(b * NTOK + q0 + row) * 3;
        qcx[rr] = __ldg(cp + 0); qcy[rr] = __ldg(cp + 1); qcz[rr] = __ldg(cp + 2);
    }

    float o[2][6][4];
    #pragma unroll
    for (int mt = 0; mt < 2; mt++)
        #pragma unroll
        for (int nb = 0; nb < 6; nb++)
            #pragma unroll
            for (int e = 0; e < 4; e++) o[mt][nb][e] = 0.f;

    float lsum[4] = {0.f, 0.f, 0.f, 0.f};

    for (int it = 0; it < N_ITERS; ++it) {
        __syncthreads();

        #pragma unroll
        for (int ii = 0; ii < 3; ii++) {
            const int idx = tid + 256 * ii;
            const int r = idx / 12, c4 = (idx % 12) * 4;
            const int kwi = r * KSTR + (c4 >> 1);
            sKh[kwi] = pack_f16(pK[ii].x, pK[ii].y);
            sKh[kwi + 1] = pack_f16(pK[ii].z, pK[ii].w);
        }
        #pragma unroll
        for (int ii = 0; ii < 3; ii++) {
            const int p = tid + 256 * ii;
            const int kp = p / 24, dp = p % 24;
            const int d = 2 * dp;
            sVh[d * VSTR + kp]       = pack_f16(pV[2 * ii].x, pV[2 * ii + 1].x);
            sVh[(d + 1) * VSTR + kp] = pack_f16(pV[2 * ii].y, pV[2 * ii + 1].y);
        }
        if (tid < 192) sC[tid % 3][tid / 3] = pC;
        __syncthreads();

        if (it + 1 < N_ITERS) {
            const int j1 = (it + 1) * TJ;
            #pragma unroll
            for (int ii = 0; ii < 3; ii++) {
                const int idx = tid + 256 * ii;
                const int r = idx / 12, c4 = (idx % 12) * 4;
                pK[ii] = __ldg(reinterpret_cast<const float4*>(gKbase + (size_t)(j1 + r) * QKV_COLS + c4));
            }
            #pragma unroll
            for (int ii = 0; ii < 3; ii++) {
                const int p = tid + 256 * ii;
                const int kp = p / 24, dp = p % 24;
                pV[2 * ii]     = __ldg(reinterpret_cast<const float2*>(gVbase + (size_t)(j1 + 2 * kp) * QKV_COLS + 2 * dp));
                pV[2 * ii + 1] = __ldg(reinterpret_cast<const float2*>(gVbase + (size_t)(j1 + 2 * kp + 1) * QKV_COLS + 2 * dp));
            }
            if (tid < 192) {
                pC = __ldg(coords + (size_t)(b * NTOK + j1 + tid / 3) * 3 + (tid % 3));
            }
        }

        float s[2][8][4];
        #pragma unroll
        for (int mt = 0; mt < 2; mt++)
            #pragma unroll
            for (int nb = 0; nb < 8; nb++)
                #pragma unroll
                for (int e = 0; e < 4; e++) s[mt][nb][e] = 0.f;

        #pragma unroll
        for (int kb = 0; kb < 3; kb++) {
            #pragma unroll
            for (int nbp = 0; nbp < 4; nbp++) {
                const int nb0 = 2 * nbp, nb1 = 2 * nbp + 1;
                const int kb0 = (8 * nb0 + g) * KSTR + 8 * kb;
                const int kb1 = (8 * nb1 + g) * KSTR + 8 * kb;
                uint32_t b0h[2], b1h[2];
                b0h[0] = sKh[kb0 + t]; b0h[1] = sKh[kb0 + t + 4];
                b1h[0] = sKh[kb1 + t]; b1h[1] = sKh[kb1 + t + 4];
                mma_f16(s[0][nb0], qh[0][kb], b0h);
                mma_f16(s[0][nb1], qh[0][kb], b1h);
                mma_f16(s[1][nb0], qh[1][kb], b0h);
                mma_f16(s[1][nb1], qh[1][kb], b1h);
            }
        }

        #pragma unroll
        for (int kb = 0; kb < 4; kb++) {
            #pragma unroll
            for (int nbo = 0; nbo < 2; nbo++) {
                const int nb = 2 * kb + nbo;
                const int c0 = 8 * nb + 2 * t;
                const float kx0 = sC[0][c0], ky0 = sC[1][c0], kz0 = sC[2][c0];
                const float kx1 = sC[0][c0 + 1], ky1 = sC[1][c0 + 1], kz1 = sC[2][c0 + 1];
                #pragma unroll
                for (int mt = 0; mt < 2; mt++) {
                    #pragma unroll
                    for (int half = 0; half < 2; half++) {
                        const int rr = 2 * mt + half;
                        float dx0 = qcx[rr] - kx0, dy0 = qcy[rr] - ky0, dz0 = qcz[rr] - kz0;
                        float dx1 = qcx[rr] - kx1, dy1 = qcy[rr] - ky1, dz1 = qcz[rr] - kz1;
                        float d0 = sqrt_approx(fmaf(dx0, dx0, fmaf(dy0, dy0, dz0 * dz0)));
                        float d1 = sqrt_approx(fmaf(dx1, dx1, fmaf(dy1, dy1, dz1 * dz1)));
                        float p0 = ex2_approx(fmaf(wd2, d0, s[mt][nb][2 * half]));
                        float p1 = ex2_approx(fmaf(wd2, d1, s[mt][nb][2 * half + 1]));
                        s[mt][nb][2 * half] = p0;
                        s[mt][nb][2 * half + 1] = p1;
                        lsum[rr] += p0 + p1;
                    }
                }
            }
            uint32_t ah[2][4];
            #pragma unroll
            for (int mt = 0; mt < 2; mt++) {
                ah[mt][0] = pack_f16(s[mt][2 * kb][0],     s[mt][2 * kb][1]);
                ah[mt][1] = pack_f16(s[mt][2 * kb][2],     s[mt][2 * kb][3]);
                ah[mt][2] = pack_f16(s[mt][2 * kb + 1][0], s[mt][2 * kb + 1][1]);
                ah[mt][3] = pack_f16(s[mt][2 * kb + 1][2], s[mt][2 * kb + 1][3]);
            }
            #pragma unroll
            for (int nbp = 0; nbp < 3; nbp++) {
                const int nb0 = 2 * nbp, nb1 = 2 * nbp + 1;
                const int vb0 = (8 * nb0 + g) * VSTR + 8 * kb;
                const int vb1 = (8 * nb1 + g) * VSTR + 8 * kb;
                uint32_t v0h[2], v1h[2];
                v0h[0] = sVh[vb0 + t]; v0h[1] = sVh[vb0 + t + 4];
                v1h[0] = sVh[vb1 + t]; v1h[1] = sVh[vb1 + t + 4];
                mma_f16(o[0][nb0], ah[0], v0h);
                mma_f16(o[0][nb1], ah[0], v1h);
                mma_f16(o[1][nb0], ah[1], v0h);
                mma_f16(o[1][nb1], ah[1], v1h);
            }
        }
    }

    #pragma unroll
    for (int rr = 0; rr < 4; rr++) {
        lsum[rr] += __shfl_xor_sync(0xffffffffu, lsum[rr], 1);
        lsum[rr] += __shfl_xor_sync(0xffffffffu, lsum[rr], 2);
        lsum[rr] = 1.f / lsum[rr];
    }

    #pragma unroll
    for (int mt = 0; mt < 2; mt++) {
        const int rowA = 32 * w + 16 * mt + g;
        float* oA = out + (size_t)(b * NTOK + q0 + rowA) * D_MODEL + h * HEAD_DIM;
        float* oB = oA + (size_t)8 * D_MODEL;
        const float invA = lsum[2 * mt], invB = lsum[2 * mt + 1];
        #pragma unroll
        for (int nb = 0; nb < 6; nb++) {
            float2 vA = make_float2(o[mt][nb][0] * invA, o[mt][nb][1] * invA);
            float2 vB = make_float2(o[mt][nb][2] * invB, o[mt][nb][3] * invB);
            *reinterpret_cast<float2*>(oA + 8 * nb + 2 * t) = vA;
            *reinterpret_cast<float2*>(oB + 8 * nb + 2 * t) = vB;
        }
    }
}

// ---------------------------------------------------------------------------
extern "C" void kernel_launch(void* const* d_in, const int* in_sizes, int n_in,
                              void* d_out, int out_size)
{
    const float* x      = (const float*)d_in[0];
    const float* coords = (const float*)d_in[1];
    const float* W_qkv  = (const float*)d_in[2];
    const float* b_qkv  = (const float*)d_in[3];
    const float* W_dist = (const float*)d_in[4];
    const float* W_out  = (const float*)d_in[6];
    const float* b_out  = (const float*)d_in[7];
    float* out = (float*)d_out;

    __half *xh, *xl, *oh, *ol;
    float *qkvf, *attnf;
    uint32_t *wqt, *wot;
    cudaGetSymbolAddress((void**)&xh, g_xh);
    cudaGetSymbolAddress((void**)&xl, g_xl);
    cudaGetSymbolAddress((void**)&wqt, g_wqt);
    cudaGetSymbolAddress((void**)&wot, g_wot);
    cudaGetSymbolAddress((void**)&qkvf, g_qkv);
    cudaGetSymbolAddress((void**)&attnf, g_attn);
    cudaGetSymbolAddress((void**)&oh, g_oh);
    cudaGetSymbolAddress((void**)&ol, g_ol);

    cudaFuncSetAttribute(gemm_h_kernel,
                         cudaFuncAttributeMaxDynamicSharedMemorySize, SMEM_GEMM);

    // 0) conversions
    split_x_kernel<<<(TOTAL_TOK * D_MODEL / 2 + 255) / 256, 256>>>(x, xh, xl, TOTAL_TOK * D_MODEL / 2);
    wtrans_kernel<<<(QKV_COLS * (D_MODEL / 2) + 255) / 256, 256>>>(W_qkv, wqt, QKV_COLS, D_MODEL);
    wtrans_kernel<<<(D_MODEL * (D_MODEL / 2) + 255) / 256, 256>>>(W_out, wot, D_MODEL, D_MODEL);

    // 1) QKV projection -> fp32; q,k cols single-term, v cols 2-term
    {
        dim3 grid(QKV_COLS / GBN, TOTAL_TOK / GBM);
        gemm_h_kernel<<<grid, 256, SMEM_GEMM>>>(xh, xl, wqt, b_qkv, qkvf,
                                                TOTAL_TOK, QKV_COLS, D_MODEL,
                                                2 * D_MODEL);
    }

    // 2) fused attention (R10 kernel, fp32 -> fp32)
    {
        dim3 grid(NTOK / MQ, BATCH * N_HEADS);
        attn_mma_kernel<<<grid, 256>>>(qkvf, coords, W_dist, attnf);
    }

    // 2b) split attention output for the out-projection
    split_x_kernel<<<(TOTAL_TOK * D_MODEL / 2 + 255) / 256, 256>>>(attnf, oh, ol, TOTAL_TOK * D_MODEL / 2);

    // 3) Output projection (all 2-term) -> fp32
    {
        dim3 grid(D_MODEL / GBN, TOTAL_TOK / GBM);
        gemm_h_kernel<<<grid, 256, SMEM_GEMM>>>(oh, ol, wot, b_out, out,
                                                TOTAL_TOK, D_MODEL, D_MODEL, 0);
    }
}

// round 16
// speedup vs baseline: 1.0489x; 1.0474x over previous
#include <cuda_runtime.h>
#include <cuda_bf16.h>
#include <cuda_fp16.h>
#include <cstdint>
#include <math.h>

#define D_MODEL 384
#define N_HEADS 8
#define HEAD_DIM 48
#define BATCH 2
#define NTOK 2048
#define TOTAL_TOK (BATCH * NTOK)
#define QKV_COLS (3 * D_MODEL)

// Scratch (allocation-free)
__device__ __half   g_xh[TOTAL_TOK * D_MODEL];
__device__ __half   g_xl[TOTAL_TOK * D_MODEL];
__device__ uint32_t g_wqt[QKV_COLS * (D_MODEL / 2)];   // [n][kp] half2
__device__ uint32_t g_wot[D_MODEL * (D_MODEL / 2)];
__device__ float    g_qkv[TOTAL_TOK * QKV_COLS];
__device__ __half   g_oh[TOTAL_TOK * D_MODEL];
__device__ __half   g_ol[TOTAL_TOK * D_MODEL];

// ---------------------------------------------------------------------------
// helpers
// ---------------------------------------------------------------------------
__device__ __forceinline__ void mma_f16(float* d, const uint32_t* a, const uint32_t* b) {
    asm volatile(
        "mma.sync.aligned.m16n8k16.row.col.f32.f16.f16.f32 "
        "{%0,%1,%2,%3}, {%4,%5,%6,%7}, {%8,%9}, {%0,%1,%2,%3};"
        : "+f"(d[0]), "+f"(d[1]), "+f"(d[2]), "+f"(d[3])
        : "r"(a[0]), "r"(a[1]), "r"(a[2]), "r"(a[3]), "r"(b[0]), "r"(b[1]));
}

__device__ __forceinline__ uint32_t pack_f16(float x, float y) {
    uint32_t r; asm("cvt.rn.f16x2.f32 %0, %1, %2;" : "=r"(r) : "f"(y), "f"(x)); return r;
}
__device__ __forceinline__ void split_pair_f16(float v0, float v1, uint32_t& hi, uint32_t& lo) {
    hi = pack_f16(v0, v1);
    __half2 h2 = *reinterpret_cast<__half2*>(&hi);
    float2 back = __half22float2(h2);
    lo = pack_f16(v0 - back.x, v1 - back.y);
}

__device__ __forceinline__ float sqrt_approx(float x) {
    float r; asm("sqrt.approx.f32 %0, %1;" : "=f"(r) : "f"(x)); return r;
}
__device__ __forceinline__ float ex2_approx(float x) {
    float r; asm("ex2.approx.f32 %0, %1;" : "=f"(r) : "f"(x)); return r;
}
__device__ __forceinline__ uint32_t smem_u32p(const void* p) {
    uint32_t a;
    asm("{ .reg .u64 t; cvta.to.shared.u64 t, %1; cvt.u32.u64 %0, t; }" : "=r"(a) : "l"(p));
    return a;
}
#define CP_ASYNC16(dst, src) \
    asm volatile("cp.async.cg.shared.global [%0], [%1], 16;" :: "r"(dst), "l"(src) : "memory")
#define CP_COMMIT() asm volatile("cp.async.commit_group;" ::: "memory")
#define CP_WAIT(n)  asm volatile("cp.async.wait_group %0;" :: "n"(n) : "memory")

// ---------------------------------------------------------------------------
// merged prep kernel: split x -> (xh, xl); transpose-pack W_qkv, W_out
// job A: i in [0, NA)        : split_x pair i
// job B: i in [NA, NA+NB)    : wtrans W_qkv item
// job C: i in [NA+NB, total) : wtrans W_out item
// ---------------------------------------------------------------------------
#define PREP_NA (TOTAL_TOK * D_MODEL / 2)              // 786432
#define PREP_NB (QKV_COLS * (D_MODEL / 2))             // 221184
#define PREP_NC (D_MODEL * (D_MODEL / 2))              // 73728
#define PREP_TOTAL (PREP_NA + PREP_NB + PREP_NC)

__global__ __launch_bounds__(256)
void prep_kernel(const float* __restrict__ x, __half* __restrict__ xh, __half* __restrict__ xl,
                 const float* __restrict__ Wq, uint32_t* __restrict__ Wqt,
                 const float* __restrict__ Wo, uint32_t* __restrict__ Wot)
{
    int i = blockIdx.x * 256 + threadIdx.x;
    if (i < PREP_NA) {
        float2 v = *reinterpret_cast<const float2*>(x + 2 * (size_t)i);
        uint32_t hi, lo;
        split_pair_f16(v.x, v.y, hi, lo);
        *reinterpret_cast<uint32_t*>(xh + 2 * (size_t)i) = hi;
        *reinterpret_cast<uint32_t*>(xl + 2 * (size_t)i) = lo;
    } else if (i < PREP_NA + PREP_NB) {
        int idx = i - PREP_NA;
        int n = idx % QKV_COLS;
        int kp = idx / QKV_COLS;
        float b0 = __ldg(Wq + (size_t)(2 * kp) * QKV_COLS + n);
        float b1 = __ldg(Wq + (size_t)(2 * kp + 1) * QKV_COLS + n);
        Wqt[(size_t)n * (D_MODEL / 2) + kp] = pack_f16(b0, b1);
    } else if (i < PREP_TOTAL) {
        int idx = i - PREP_NA - PREP_NB;
        int n = idx % D_MODEL;
        int kp = idx / D_MODEL;
        float b0 = __ldg(Wo + (size_t)(2 * kp) * D_MODEL + n);
        float b1 = __ldg(Wo + (size_t)(2 * kp + 1) * D_MODEL + n);
        Wot[(size_t)n * (D_MODEL / 2) + kp] = pack_f16(b0, b1);
    }
}

// ---------------------------------------------------------------------------
// FP16 GEMM, cp.async double-buffered; columns >= two_term_from get Al term.
// ---------------------------------------------------------------------------
#define GBM 128
#define GBN 64
#define GBK 32
#define ASTR 20
#define BSTR 20
#define A_TILE_U32 (GBM * ASTR)
#define B_TILE_U32 (GBN * BSTR)
#define SMEM_GEMM ((2 * A_TILE_U32 * 2 + 2 * B_TILE_U32) * 4)

__global__ __launch_bounds__(256)
void gemm_h_kernel(const __half* __restrict__ Ah, const __half* __restrict__ Al,
                   const uint32_t* __restrict__ Bt, const float* __restrict__ bias,
                   float* __restrict__ C, int M, int N, int K, int two_term_from)
{
    extern __shared__ uint32_t smem[];
    uint32_t* sAh = smem;
    uint32_t* sAl = smem + 2 * A_TILE_U32;
    uint32_t* sBh = smem + 4 * A_TILE_U32;

    const int tid = threadIdx.x;
    const int w = tid >> 5;
    const int lane = tid & 31;
    const int g = lane >> 2;
    const int t = lane & 3;
    const int wm = w >> 1;
    const int wn = w & 1;
    const int row0 = blockIdx.y * GBM;
    const int col0 = blockIdx.x * GBN;
    const int Kp = K / 2;
    const int NT = K / GBK;
    const bool two_term = (col0 >= two_term_from);

    const int a_r0 = (tid + 0)   >> 2, a_q0 = (tid + 0)   & 3;
    const int a_r1 = (tid + 256) >> 2, a_q1 = (tid + 256) & 3;
    const int b_n = tid >> 2, b_q = tid & 3;

    auto stage = [&](int k0, int buf) {
        uint32_t d;
        d = smem_u32p(&sAh[buf * A_TILE_U32 + a_r0 * ASTR + 4 * a_q0]);
        CP_ASYNC16(d, Ah + (size_t)(row0 + a_r0) * K + k0 + 8 * a_q0);
        d = smem_u32p(&sAh[buf * A_TILE_U32 + a_r1 * ASTR + 4 * a_q1]);
        CP_ASYNC16(d, Ah + (size_t)(row0 + a_r1) * K + k0 + 8 * a_q1);
        if (two_term) {
            d = smem_u32p(&sAl[buf * A_TILE_U32 + a_r0 * ASTR + 4 * a_q0]);
            CP_ASYNC16(d, Al + (size_t)(row0 + a_r0) * K + k0 + 8 * a_q0);
            d = smem_u32p(&sAl[buf * A_TILE_U32 + a_r1 * ASTR + 4 * a_q1]);
            CP_ASYNC16(d, Al + (size_t)(row0 + a_r1) * K + k0 + 8 * a_q1);
        }
        d = smem_u32p(&sBh[buf * B_TILE_U32 + b_n * BSTR + 4 * b_q]);
        CP_ASYNC16(d, Bt + (size_t)(col0 + b_n) * Kp + (k0 >> 1) + 4 * b_q);
        CP_COMMIT();
    };

    float acc[2][4][4];
    #pragma unroll
    for (int mt = 0; mt < 2; mt++)
        #pragma unroll
        for (int nb = 0; nb < 4; nb++)
            #pragma unroll
            for (int e = 0; e < 4; e++) acc[mt][nb][e] = 0.f;

    stage(0, 0);

    for (int kt = 0; kt < NT; kt++) {
        const int buf = kt & 1;
        if (kt + 1 < NT) {
            stage((kt + 1) * GBK, (kt + 1) & 1);
            CP_WAIT(1);
        } else {
            CP_WAIT(0);
        }
        __syncthreads();

        const uint32_t* cAh = sAh + buf * A_TILE_U32;
        const uint32_t* cAl = sAl + buf * A_TILE_U32;
        const uint32_t* cBh = sBh + buf * B_TILE_U32;

        #pragma unroll
        for (int kc = 0; kc < 2; kc++) {
            uint32_t ah[2][4], al[2][4];
            #pragma unroll
            for (int mt = 0; mt < 2; mt++) {
                const int rA = (32 * wm + 16 * mt + g) * ASTR + 8 * kc;
                const int rB = rA + 8 * ASTR;
                ah[mt][0] = cAh[rA + t];
                ah[mt][1] = cAh[rB + t];
                ah[mt][2] = cAh[rA + t + 4];
                ah[mt][3] = cAh[rB + t + 4];
                if (two_term) {
                    al[mt][0] = cAl[rA + t];
                    al[mt][1] = cAl[rB + t];
                    al[mt][2] = cAl[rA + t + 4];
                    al[mt][3] = cAl[rB + t + 4];
                }
            }
            #pragma unroll
            for (int nb = 0; nb < 4; nb++) {
                const int nbase = (32 * wn + 8 * nb + g) * BSTR + 8 * kc;
                uint32_t bh_[2];
                bh_[0] = cBh[nbase + t];
                bh_[1] = cBh[nbase + t + 4];
                mma_f16(acc[0][nb], ah[0], bh_);
                mma_f16(acc[1][nb], ah[1], bh_);
                if (two_term) {
                    mma_f16(acc[0][nb], al[0], bh_);
                    mma_f16(acc[1][nb], al[1], bh_);
                }
            }
        }
        __syncthreads();
    }

    #pragma unroll
    for (int mt = 0; mt < 2; mt++) {
        const int rA = row0 + 32 * wm + 16 * mt + g;
        #pragma unroll
        for (int nb = 0; nb < 4; nb++) {
            const int c = col0 + 32 * wn + 8 * nb + 2 * t;
            const float bx = bias[c], by = bias[c + 1];
            *reinterpret_cast<float2*>(C + (size_t)rA * N + c) =
                make_float2(acc[mt][nb][0] + bx, acc[mt][nb][1] + by);
            *reinterpret_cast<float2*>(C + (size_t)(rA + 8) * N + c) =
                make_float2(acc[mt][nb][2] + bx, acc[mt][nb][3] + by);
        }
    }
}

// ---------------------------------------------------------------------------
// Fused attention — R10/R15 body (float2/float4 prefetch, pack-to-fp16
// staging, f32 softmax); epilogue writes hi/lo split halves directly.
// ---------------------------------------------------------------------------
#define TJ 64
#define MQ 256
#define N_ITERS (NTOK / TJ)
#define KSTR 28
#define VSTR 36
#define LOG2E 1.4426950408889634f

__global__ __launch_bounds__(256, 1)
void attn_mma_kernel(const float* __restrict__ qkv, const float* __restrict__ coords,
                     const float* __restrict__ W_dist,
                     __half* __restrict__ oh, __half* __restrict__ ol)
{
    __shared__ uint32_t sKh[TJ * KSTR];
    __shared__ uint32_t sVh[HEAD_DIM * VSTR];
    __shared__ float sC[3][TJ];

    const int tid = threadIdx.x;
    const int w = tid >> 5;
    const int lane = tid & 31;
    const int g = lane >> 2;
    const int t = lane & 3;
    const int bh = blockIdx.y;
    const int b = bh >> 3, h = bh & 7;
    const int q0 = blockIdx.x * MQ;

    const float qscale = 0.14433756729740643f * LOG2E;
    const float wd2 = __ldg(W_dist + h) * LOG2E;

    const float* gKbase = qkv + (size_t)(b * NTOK) * QKV_COLS + D_MODEL + h * HEAD_DIM;
    const float* gVbase = gKbase + D_MODEL;

    float4 pK[3];
    float2 pV[6];
    float pC = 0.f;

    #pragma unroll
    for (int ii = 0; ii < 3; ii++) {
        const int idx = tid + 256 * ii;
        const int r = idx / 12, c4 = (idx % 12) * 4;
        pK[ii] = __ldg(reinterpret_cast<const float4*>(gKbase + (size_t)r * QKV_COLS + c4));
    }
    #pragma unroll
    for (int ii = 0; ii < 3; ii++) {
        const int p = tid + 256 * ii;
        const int kp = p / 24, dp = p % 24;
        pV[2 * ii]     = __ldg(reinterpret_cast<const float2*>(gVbase + (size_t)(2 * kp) * QKV_COLS + 2 * dp));
        pV[2 * ii + 1] = __ldg(reinterpret_cast<const float2*>(gVbase + (size_t)(2 * kp + 1) * QKV_COLS + 2 * dp));
    }
    if (tid < 192) {
        pC = __ldg(coords + (size_t)(b * NTOK + tid / 3) * 3 + (tid % 3));
    }

    uint32_t qh[2][3][4];
    {
        const float* gQ = qkv + (size_t)(b * NTOK + q0) * QKV_COLS + h * HEAD_DIM;
        #pragma unroll
        for (int mt = 0; mt < 2; mt++) {
            const int rA = 32 * w + 16 * mt + g;
            #pragma unroll
            for (int kb = 0; kb < 3; kb++) {
                const int c = 16 * kb + 2 * t;
                float2 v0 = __ldg(reinterpret_cast<const float2*>(gQ + (size_t)rA * QKV_COLS + c));
                float2 v1 = __ldg(reinterpret_cast<const float2*>(gQ + (size_t)(rA + 8) * QKV_COLS + c));
                float2 v2 = __ldg(reinterpret_cast<const float2*>(gQ + (size_t)rA * QKV_COLS + c + 8));
                float2 v3 = __ldg(reinterpret_cast<const float2*>(gQ + (size_t)(rA + 8) * QKV_COLS + c + 8));
                qh[mt][kb][0] = pack_f16(v0.x * qscale, v0.y * qscale);
                qh[mt][kb][1] = pack_f16(v1.x * qscale, v1.y * qscale);
                qh[mt][kb][2] = pack_f16(v2.x * qscale, v2.y * qscale);
                qh[mt][kb][3] = pack_f16(v3.x * qscale, v3.y * qscale);
            }
        }
    }

    float qcx[4], qcy[4], qcz[4];
    #pragma unroll
    for (int rr = 0; rr < 4; rr++) {
        const int row = 32 * w + 8 * rr + g;
        const float* cp = coords + (size_t)(b * NTOK + q0 + row) * 3;
        qcx[rr] = __ldg(cp + 0); qcy[rr] = __ldg(cp + 1); qcz[rr] = __ldg(cp + 2);
    }

    float o[2][6][4];
    #pragma unroll
    for (int mt = 0; mt < 2; mt++)
        #pragma unroll
        for (int nb = 0; nb < 6; nb++)
            #pragma unroll
            for (int e = 0; e < 4; e++) o[mt][nb][e] = 0.f;

    float lsum[4] = {0.f, 0.f, 0.f, 0.f};

    for (int it = 0; it < N_ITERS; ++it) {
        __syncthreads();

        #pragma unroll
        for (int ii = 0; ii < 3; ii++) {
            const int idx = tid + 256 * ii;
            const int r = idx / 12, c4 = (idx % 12) * 4;
            const int kwi = r * KSTR + (c4 >> 1);
            sKh[kwi] = pack_f16(pK[ii].x, pK[ii].y);
            sKh[kwi + 1] = pack_f16(pK[ii].z, pK[ii].w);
        }
        #pragma unroll
        for (int ii = 0; ii < 3; ii++) {
            const int p = tid + 256 * ii;
            const int kp = p / 24, dp = p % 24;
            const int d = 2 * dp;
            sVh[d * VSTR + kp]       = pack_f16(pV[2 * ii].x, pV[2 * ii + 1].x);
            sVh[(d + 1) * VSTR + kp] = pack_f16(pV[2 * ii].y, pV[2 * ii + 1].y);
        }
        if (tid < 192) sC[tid % 3][tid / 3] = pC;
        __syncthreads();

        if (it + 1 < N_ITERS) {
            const int j1 = (it + 1) * TJ;
            #pragma unroll
            for (int ii = 0; ii < 3; ii++) {
                const int idx = tid + 256 * ii;
                const int r = idx / 12, c4 = (idx % 12) * 4;
                pK[ii] = __ldg(reinterpret_cast<const float4*>(gKbase + (size_t)(j1 + r) * QKV_COLS + c4));
            }
            #pragma unroll
            for (int ii = 0; ii < 3; ii++) {
                const int p = tid + 256 * ii;
                const int kp = p / 24, dp = p % 24;
                pV[2 * ii]     = __ldg(reinterpret_cast<const float2*>(gVbase + (size_t)(j1 + 2 * kp) * QKV_COLS + 2 * dp));
                pV[2 * ii + 1] = __ldg(reinterpret_cast<const float2*>(gVbase + (size_t)(j1 + 2 * kp + 1) * QKV_COLS + 2 * dp));
            }
            if (tid < 192) {
                pC = __ldg(coords + (size_t)(b * NTOK + j1 + tid / 3) * 3 + (tid % 3));
            }
        }

        float s[2][8][4];
        #pragma unroll
        for (int mt = 0; mt < 2; mt++)
            #pragma unroll
            for (int nb = 0; nb < 8; nb++)
                #pragma unroll
                for (int e = 0; e < 4; e++) s[mt][nb][e] = 0.f;

        #pragma unroll
        for (int kb = 0; kb < 3; kb++) {
            #pragma unroll
            for (int nbp = 0; nbp < 4; nbp++) {
                const int nb0 = 2 * nbp, nb1 = 2 * nbp + 1;
                const int kb0 = (8 * nb0 + g) * KSTR + 8 * kb;
                const int kb1 = (8 * nb1 + g) * KSTR + 8 * kb;
                uint32_t b0h[2], b1h[2];
                b0h[0] = sKh[kb0 + t]; b0h[1] = sKh[kb0 + t + 4];
                b1h[0] = sKh[kb1 + t]; b1h[1] = sKh[kb1 + t + 4];
                mma_f16(s[0][nb0], qh[0][kb], b0h);
                mma_f16(s[0][nb1], qh[0][kb], b1h);
                mma_f16(s[1][nb0], qh[1][kb], b0h);
                mma_f16(s[1][nb1], qh[1][kb], b1h);
            }
        }

        #pragma unroll
        for (int kb = 0; kb < 4; kb++) {
            #pragma unroll
            for (int nbo = 0; nbo < 2; nbo++) {
                const int nb = 2 * kb + nbo;
                const int c0 = 8 * nb + 2 * t;
                const float kx0 = sC[0][c0], ky0 = sC[1][c0], kz0 = sC[2][c0];
                const float kx1 = sC[0][c0 + 1], ky1 = sC[1][c0 + 1], kz1 = sC[2][c0 + 1];
                #pragma unroll
                for (int mt = 0; mt < 2; mt++) {
                    #pragma unroll
                    for (int half = 0; half < 2; half++) {
                        const int rr = 2 * mt + half;
                        float dx0 = qcx[rr] - kx0, dy0 = qcy[rr] - ky0, dz0 = qcz[rr] - kz0;
                        float dx1 = qcx[rr] - kx1, dy1 = qcy[rr] - ky1, dz1 = qcz[rr] - kz1;
                        float d0 = sqrt_approx(fmaf(dx0, dx0, fmaf(dy0, dy0, dz0 * dz0)));
                        float d1 = sqrt_approx(fmaf(dx1, dx1, fmaf(dy1, dy1, dz1 * dz1)));
                        float p0 = ex2_approx(fmaf(wd2, d0, s[mt][nb][2 * half]));
                        float p1 = ex2_approx(fmaf(wd2, d1, s[mt][nb][2 * half + 1]));
                        s[mt][nb][2 * half] = p0;
                        s[mt][nb][2 * half + 1] = p1;
                        lsum[rr] += p0 + p1;
                    }
                }
            }
            uint32_t ah[2][4];
            #pragma unroll
            for (int mt = 0; mt < 2; mt++) {
                ah[mt][0] = pack_f16(s[mt][2 * kb][0],     s[mt][2 * kb][1]);
                ah[mt][1] = pack_f16(s[mt][2 * kb][2],     s[mt][2 * kb][3]);
                ah[mt][2] = pack_f16(s[mt][2 * kb + 1][0], s[mt][2 * kb + 1][1]);
                ah[mt][3] = pack_f16(s[mt][2 * kb + 1][2], s[mt][2 * kb + 1][3]);
            }
            #pragma unroll
            for (int nbp = 0; nbp < 3; nbp++) {
                const int nb0 = 2 * nbp, nb1 = 2 * nbp + 1;
                const int vb0 = (8 * nb0 + g) * VSTR + 8 * kb;
                const int vb1 = (8 * nb1 + g) * VSTR + 8 * kb;
                uint32_t v0h[2], v1h[2];
                v0h[0] = sVh[vb0 + t]; v0h[1] = sVh[vb0 + t + 4];
                v1h[0] = sVh[vb1 + t]; v1h[1] = sVh[vb1 + t + 4];
                mma_f16(o[0][nb0], ah[0], v0h);
                mma_f16(o[0][nb1], ah[0], v1h);
                mma_f16(o[1][nb0], ah[1], v0h);
                mma_f16(o[1][nb1], ah[1], v1h);
            }
        }
    }

    #pragma unroll
    for (int rr = 0; rr < 4; rr++) {
        lsum[rr] += __shfl_xor_sync(0xffffffffu, lsum[rr], 1);
        lsum[rr] += __shfl_xor_sync(0xffffffffu, lsum[rr], 2);
        lsum[rr] = 1.f / lsum[rr];
    }

    // epilogue: write hi/lo split halves directly (feeds out-projection)
    #pragma unroll
    for (int mt = 0; mt < 2; mt++) {
        const int rowA = 32 * w + 16 * mt + g;
        const size_t baseA = (size_t)(b * NTOK + q0 + rowA) * D_MODEL + h * HEAD_DIM;
        const size_t baseB = baseA + (size_t)8 * D_MODEL;
        const float invA = lsum[2 * mt], invB = lsum[2 * mt + 1];
        #pragma unroll
        for (int nb = 0; nb < 6; nb++) {
            const int c = 8 * nb + 2 * t;
            uint32_t hiA, loA, hiB, loB;
            split_pair_f16(o[mt][nb][0] * invA, o[mt][nb][1] * invA, hiA, loA);
            split_pair_f16(o[mt][nb][2] * invB, o[mt][nb][3] * invB, hiB, loB);
            *reinterpret_cast<uint32_t*>(oh + baseA + c) = hiA;
            *reinterpret_cast<uint32_t*>(ol + baseA + c) = loA;
            *reinterpret_cast<uint32_t*>(oh + baseB + c) = hiB;
            *reinterpret_cast<uint32_t*>(ol + baseB + c) = loB;
        }
    }
}

// ---------------------------------------------------------------------------
extern "C" void kernel_launch(void* const* d_in, const int* in_sizes, int n_in,
                              void* d_out, int out_size)
{
    const float* x      = (const float*)d_in[0];
    const float* coords = (const float*)d_in[1];
    const float* W_qkv  = (const float*)d_in[2];
    const float* b_qkv  = (const float*)d_in[3];
    const float* W_dist = (const float*)d_in[4];
    const float* W_out  = (const float*)d_in[6];
    const float* b_out  = (const float*)d_in[7];
    float* out = (float*)d_out;

    __half *xh, *xl, *oh, *ol;
    float* qkvf;
    uint32_t *wqt, *wot;
    cudaGetSymbolAddress((void**)&xh, g_xh);
    cudaGetSymbolAddress((void**)&xl, g_xl);
    cudaGetSymbolAddress((void**)&wqt, g_wqt);
    cudaGetSymbolAddress((void**)&wot, g_wot);
    cudaGetSymbolAddress((void**)&qkvf, g_qkv);
    cudaGetSymbolAddress((void**)&oh, g_oh);
    cudaGetSymbolAddress((void**)&ol, g_ol);

    cudaFuncSetAttribute(gemm_h_kernel,
                         cudaFuncAttributeMaxDynamicSharedMemorySize, SMEM_GEMM);

    // 0) merged prep: split x + transpose-pack both weight matrices
    prep_kernel<<<(PREP_TOTAL + 255) / 256, 256>>>(x, xh, xl, W_qkv, wqt, W_out, wot);

    // 1) QKV projection -> fp32; q,k cols single-term, v cols 2-term
    {
        dim3 grid(QKV_COLS / GBN, TOTAL_TOK / GBM);
        gemm_h_kernel<<<grid, 256, SMEM_GEMM>>>(xh, xl, wqt, b_qkv, qkvf,
                                                TOTAL_TOK, QKV_COLS, D_MODEL,
                                                2 * D_MODEL);
    }

    // 2) fused attention (R10 body) -> split fp16 halves
    {
        dim3 grid(NTOK / MQ, BATCH * N_HEADS);
        attn_mma_kernel<<<grid, 256>>>(qkvf, coords, W_dist, oh, ol);
    }

    // 3) Output projection (all 2-term) -> fp32
    {
        dim3 grid(D_MODEL / GBN, TOTAL_TOK / GBM);
        gemm_h_kernel<<<grid, 256, SMEM_GEMM>>>(oh, ol, wot, b_out, out,
                                                TOTAL_TOK, D_MODEL, D_MODEL, 0);
    }
}

// round 17
// speedup vs baseline: 1.0829x; 1.0324x over previous
#include <cuda_runtime.h>
#include <cuda_bf16.h>
#include <cuda_fp16.h>
#include <cstdint>
#include <math.h>

#define D_MODEL 384
#define N_HEADS 8
#define HEAD_DIM 48
#define BATCH 2
#define NTOK 2048
#define TOTAL_TOK (BATCH * NTOK)
#define QKV_COLS (3 * D_MODEL)

// Scratch (allocation-free)
__device__ __half   g_xh[TOTAL_TOK * D_MODEL];
__device__ __half   g_xl[TOTAL_TOK * D_MODEL];
__device__ uint32_t g_wqt[QKV_COLS * (D_MODEL / 2)];   // [n][kp] half2
__device__ uint32_t g_wot[D_MODEL * (D_MODEL / 2)];
__device__ float    g_qkv[TOTAL_TOK * QKV_COLS];
__device__ __half   g_oh[TOTAL_TOK * D_MODEL];

// ---------------------------------------------------------------------------
// helpers
// ---------------------------------------------------------------------------
__device__ __forceinline__ void mma_f16(float* d, const uint32_t* a, const uint32_t* b) {
    asm volatile(
        "mma.sync.aligned.m16n8k16.row.col.f32.f16.f16.f32 "
        "{%0,%1,%2,%3}, {%4,%5,%6,%7}, {%8,%9}, {%0,%1,%2,%3};"
        : "+f"(d[0]), "+f"(d[1]), "+f"(d[2]), "+f"(d[3])
        : "r"(a[0]), "r"(a[1]), "r"(a[2]), "r"(a[3]), "r"(b[0]), "r"(b[1]));
}

__device__ __forceinline__ uint32_t pack_f16(float x, float y) {
    uint32_t r; asm("cvt.rn.f16x2.f32 %0, %1, %2;" : "=r"(r) : "f"(y), "f"(x)); return r;
}
__device__ __forceinline__ void split_pair_f16(float v0, float v1, uint32_t& hi, uint32_t& lo) {
    hi = pack_f16(v0, v1);
    __half2 h2 = *reinterpret_cast<__half2*>(&hi);
    float2 back = __half22float2(h2);
    lo = pack_f16(v0 - back.x, v1 - back.y);
}

__device__ __forceinline__ float sqrt_approx(float x) {
    float r; asm("sqrt.approx.f32 %0, %1;" : "=f"(r) : "f"(x)); return r;
}
__device__ __forceinline__ float ex2_approx(float x) {
    float r; asm("ex2.approx.f32 %0, %1;" : "=f"(r) : "f"(x)); return r;
}
__device__ __forceinline__ uint32_t smem_u32p(const void* p) {
    uint32_t a;
    asm("{ .reg .u64 t; cvta.to.shared.u64 t, %1; cvt.u32.u64 %0, t; }" : "=r"(a) : "l"(p));
    return a;
}
#define CP_ASYNC16(dst, src) \
    asm volatile("cp.async.cg.shared.global [%0], [%1], 16;" :: "r"(dst), "l"(src) : "memory")
#define CP_COMMIT() asm volatile("cp.async.commit_group;" ::: "memory")
#define CP_WAIT(n)  asm volatile("cp.async.wait_group %0;" :: "n"(n) : "memory")

// ---------------------------------------------------------------------------
// merged prep kernel: split x -> (xh, xl); transpose-pack W_qkv, W_out
// ---------------------------------------------------------------------------
#define PREP_NA (TOTAL_TOK * D_MODEL / 2)              // 786432
#define PREP_NB (QKV_COLS * (D_MODEL / 2))             // 221184
#define PREP_NC (D_MODEL * (D_MODEL / 2))              // 73728
#define PREP_TOTAL (PREP_NA + PREP_NB + PREP_NC)

__global__ __launch_bounds__(256)
void prep_kernel(const float* __restrict__ x, __half* __restrict__ xh, __half* __restrict__ xl,
                 const float* __restrict__ Wq, uint32_t* __restrict__ Wqt,
                 const float* __restrict__ Wo, uint32_t* __restrict__ Wot)
{
    int i = blockIdx.x * 256 + threadIdx.x;
    if (i < PREP_NA) {
        float2 v = *reinterpret_cast<const float2*>(x + 2 * (size_t)i);
        uint32_t hi, lo;
        split_pair_f16(v.x, v.y, hi, lo);
        *reinterpret_cast<uint32_t*>(xh + 2 * (size_t)i) = hi;
        *reinterpret_cast<uint32_t*>(xl + 2 * (size_t)i) = lo;
    } else if (i < PREP_NA + PREP_NB) {
        int idx = i - PREP_NA;
        int n = idx % QKV_COLS;
        int kp = idx / QKV_COLS;
        float b0 = __ldg(Wq + (size_t)(2 * kp) * QKV_COLS + n);
        float b1 = __ldg(Wq + (size_t)(2 * kp + 1) * QKV_COLS + n);
        Wqt[(size_t)n * (D_MODEL / 2) + kp] = pack_f16(b0, b1);
    } else if (i < PREP_TOTAL) {
        int idx = i - PREP_NA - PREP_NB;
        int n = idx % D_MODEL;
        int kp = idx / D_MODEL;
        float b0 = __ldg(Wo + (size_t)(2 * kp) * D_MODEL + n);
        float b1 = __ldg(Wo + (size_t)(2 * kp + 1) * D_MODEL + n);
        Wot[(size_t)n * (D_MODEL / 2) + kp] = pack_f16(b0, b1);
    }
}

// ---------------------------------------------------------------------------
// FP16 GEMM, cp.async double-buffered; columns >= two_term_from get Al term.
// Pass two_term_from > N for pure single-term (Al never touched).
// ---------------------------------------------------------------------------
#define GBM 128
#define GBN 64
#define GBK 32
#define ASTR 20
#define BSTR 20
#define A_TILE_U32 (GBM * ASTR)
#define B_TILE_U32 (GBN * BSTR)
#define SMEM_GEMM ((2 * A_TILE_U32 * 2 + 2 * B_TILE_U32) * 4)

__global__ __launch_bounds__(256)
void gemm_h_kernel(const __half* __restrict__ Ah, const __half* __restrict__ Al,
                   const uint32_t* __restrict__ Bt, const float* __restrict__ bias,
                   float* __restrict__ C, int M, int N, int K, int two_term_from)
{
    extern __shared__ uint32_t smem[];
    uint32_t* sAh = smem;
    uint32_t* sAl = smem + 2 * A_TILE_U32;
    uint32_t* sBh = smem + 4 * A_TILE_U32;

    const int tid = threadIdx.x;
    const int w = tid >> 5;
    const int lane = tid & 31;
    const int g = lane >> 2;
    const int t = lane & 3;
    const int wm = w >> 1;
    const int wn = w & 1;
    const int row0 = blockIdx.y * GBM;
    const int col0 = blockIdx.x * GBN;
    const int Kp = K / 2;
    const int NT = K / GBK;
    const bool two_term = (col0 >= two_term_from);

    const int a_r0 = (tid + 0)   >> 2, a_q0 = (tid + 0)   & 3;
    const int a_r1 = (tid + 256) >> 2, a_q1 = (tid + 256) & 3;
    const int b_n = tid >> 2, b_q = tid & 3;

    auto stage = [&](int k0, int buf) {
        uint32_t d;
        d = smem_u32p(&sAh[buf * A_TILE_U32 + a_r0 * ASTR + 4 * a_q0]);
        CP_ASYNC16(d, Ah + (size_t)(row0 + a_r0) * K + k0 + 8 * a_q0);
        d = smem_u32p(&sAh[buf * A_TILE_U32 + a_r1 * ASTR + 4 * a_q1]);
        CP_ASYNC16(d, Ah + (size_t)(row0 + a_r1) * K + k0 + 8 * a_q1);
        if (two_term) {
            d = smem_u32p(&sAl[buf * A_TILE_U32 + a_r0 * ASTR + 4 * a_q0]);
            CP_ASYNC16(d, Al + (size_t)(row0 + a_r0) * K + k0 + 8 * a_q0);
            d = smem_u32p(&sAl[buf * A_TILE_U32 + a_r1 * ASTR + 4 * a_q1]);
            CP_ASYNC16(d, Al + (size_t)(row0 + a_r1) * K + k0 + 8 * a_q1);
        }
        d = smem_u32p(&sBh[buf * B_TILE_U32 + b_n * BSTR + 4 * b_q]);
        CP_ASYNC16(d, Bt + (size_t)(col0 + b_n) * Kp + (k0 >> 1) + 4 * b_q);
        CP_COMMIT();
    };

    float acc[2][4][4];
    #pragma unroll
    for (int mt = 0; mt < 2; mt++)
        #pragma unroll
        for (int nb = 0; nb < 4; nb++)
            #pragma unroll
            for (int e = 0; e < 4; e++) acc[mt][nb][e] = 0.f;

    stage(0, 0);

    for (int kt = 0; kt < NT; kt++) {
        const int buf = kt & 1;
        if (kt + 1 < NT) {
            stage((kt + 1) * GBK, (kt + 1) & 1);
            CP_WAIT(1);
        } else {
            CP_WAIT(0);
        }
        __syncthreads();

        const uint32_t* cAh = sAh + buf * A_TILE_U32;
        const uint32_t* cAl = sAl + buf * A_TILE_U32;
        const uint32_t* cBh = sBh + buf * B_TILE_U32;

        #pragma unroll
        for (int kc = 0; kc < 2; kc++) {
            uint32_t ah[2][4], al[2][4];
            #pragma unroll
            for (int mt = 0; mt < 2; mt++) {
                const int rA = (32 * wm + 16 * mt + g) * ASTR + 8 * kc;
                const int rB = rA + 8 * ASTR;
                ah[mt][0] = cAh[rA + t];
                ah[mt][1] = cAh[rB + t];
                ah[mt][2] = cAh[rA + t + 4];
                ah[mt][3] = cAh[rB + t + 4];
                if (two_term) {
                    al[mt][0] = cAl[rA + t];
                    al[mt][1] = cAl[rB + t];
                    al[mt][2] = cAl[rA + t + 4];
                    al[mt][3] = cAl[rB + t + 4];
                }
            }
            #pragma unroll
            for (int nb = 0; nb < 4; nb++) {
                const int nbase = (32 * wn + 8 * nb + g) * BSTR + 8 * kc;
                uint32_t bh_[2];
                bh_[0] = cBh[nbase + t];
                bh_[1] = cBh[nbase + t + 4];
                mma_f16(acc[0][nb], ah[0], bh_);
                mma_f16(acc[1][nb], ah[1], bh_);
                if (two_term) {
                    mma_f16(acc[0][nb], al[0], bh_);
                    mma_f16(acc[1][nb], al[1], bh_);
                }
            }
        }
        __syncthreads();
    }

    #pragma unroll
    for (int mt = 0; mt < 2; mt++) {
        const int rA = row0 + 32 * wm + 16 * mt + g;
        #pragma unroll
        for (int nb = 0; nb < 4; nb++) {
            const int c = col0 + 32 * wn + 8 * nb + 2 * t;
            const float bx = bias[c], by = bias[c + 1];
            *reinterpret_cast<float2*>(C + (size_t)rA * N + c) =
                make_float2(acc[mt][nb][0] + bx, acc[mt][nb][1] + by);
            *reinterpret_cast<float2*>(C + (size_t)(rA + 8) * N + c) =
                make_float2(acc[mt][nb][2] + bx, acc[mt][nb][3] + by);
        }
    }
}

// ---------------------------------------------------------------------------
// Fused attention — R10/R16 body; epilogue writes fp16 (hi only).
// ---------------------------------------------------------------------------
#define TJ 64
#define MQ 256
#define N_ITERS (NTOK / TJ)
#define KSTR 28
#define VSTR 36
#define LOG2E 1.4426950408889634f

__global__ __launch_bounds__(256, 1)
void attn_mma_kernel(const float* __restrict__ qkv, const float* __restrict__ coords,
                     const float* __restrict__ W_dist,
                     __half* __restrict__ oh)
{
    __shared__ uint32_t sKh[TJ * KSTR];
    __shared__ uint32_t sVh[HEAD_DIM * VSTR];
    __shared__ float sC[3][TJ];

    const int tid = threadIdx.x;
    const int w = tid >> 5;
    const int lane = tid & 31;
    const int g = lane >> 2;
    const int t = lane & 3;
    const int bh = blockIdx.y;
    const int b = bh >> 3, h = bh & 7;
    const int q0 = blockIdx.x * MQ;

    const float qscale = 0.14433756729740643f * LOG2E;
    const float wd2 = __ldg(W_dist + h) * LOG2E;

    const float* gKbase = qkv + (size_t)(b * NTOK) * QKV_COLS + D_MODEL + h * HEAD_DIM;
    const float* gVbase = gKbase + D_MODEL;

    float4 pK[3];
    float2 pV[6];
    float pC = 0.f;

    #pragma unroll
    for (int ii = 0; ii < 3; ii++) {
        const int idx = tid + 256 * ii;
        const int r = idx / 12, c4 = (idx % 12) * 4;
        pK[ii] = __ldg(reinterpret_cast<const float4*>(gKbase + (size_t)r * QKV_COLS + c4));
    }
    #pragma unroll
    for (int ii = 0; ii < 3; ii++) {
        const int p = tid + 256 * ii;
        const int kp = p / 24, dp = p % 24;
        pV[2 * ii]     = __ldg(reinterpret_cast<const float2*>(gVbase + (size_t)(2 * kp) * QKV_COLS + 2 * dp));
        pV[2 * ii + 1] = __ldg(reinterpret_cast<const float2*>(gVbase + (size_t)(2 * kp + 1) * QKV_COLS + 2 * dp));
    }
    if (tid < 192) {
        pC = __ldg(coords + (size_t)(b * NTOK + tid / 3) * 3 + (tid % 3));
    }

    uint32_t qh[2][3][4];
    {
        const float* gQ = qkv + (size_t)(b * NTOK + q0) * QKV_COLS + h * HEAD_DIM;
        #pragma unroll
        for (int mt = 0; mt < 2; mt++) {
            const int rA = 32 * w + 16 * mt + g;
            #pragma unroll
            for (int kb = 0; kb < 3; kb++) {
                const int c = 16 * kb + 2 * t;
                float2 v0 = __ldg(reinterpret_cast<const float2*>(gQ + (size_t)rA * QKV_COLS + c));
                float2 v1 = __ldg(reinterpret_cast<const float2*>(gQ + (size_t)(rA + 8) * QKV_COLS + c));
                float2 v2 = __ldg(reinterpret_cast<const float2*>(gQ + (size_t)rA * QKV_COLS + c + 8));
                float2 v3 = __ldg(reinterpret_cast<const float2*>(gQ + (size_t)(rA + 8) * QKV_COLS + c + 8));
                qh[mt][kb][0] = pack_f16(v0.x * qscale, v0.y * qscale);
                qh[mt][kb][1] = pack_f16(v1.x * qscale, v1.y * qscale);
                qh[mt][kb][2] = pack_f16(v2.x * qscale, v2.y * qscale);
                qh[mt][kb][3] = pack_f16(v3.x * qscale, v3.y * qscale);
            }
        }
    }

    float qcx[4], qcy[4], qcz[4];
    #pragma unroll
    for (int rr = 0; rr < 4; rr++) {
        const int row = 32 * w + 8 * rr + g;
        const float* cp = coords + (size_t)(b * NTOK + q0 + row) * 3;
        qcx[rr] = __ldg(cp + 0); qcy[rr] = __ldg(cp + 1); qcz[rr] = __ldg(cp + 2);
    }

    float o[2][6][4];
    #pragma unroll
    for (int mt = 0; mt < 2; mt++)
        #pragma unroll
        for (int nb = 0; nb < 6; nb++)
            #pragma unroll
            for (int e = 0; e < 4; e++) o[mt][nb][e] = 0.f;

    float lsum[4] = {0.f, 0.f, 0.f, 0.f};

    for (int it = 0; it < N_ITERS; ++it) {
        __syncthreads();

        #pragma unroll
        for (int ii = 0; ii < 3; ii++) {
            const int idx = tid + 256 * ii;
            const int r = idx / 12, c4 = (idx % 12) * 4;
            const int kwi = r * KSTR + (c4 >> 1);
            sKh[kwi] = pack_f16(pK[ii].x, pK[ii].y);
            sKh[kwi + 1] = pack_f16(pK[ii].z, pK[ii].w);
        }
        #pragma unroll
        for (int ii = 0; ii < 3; ii++) {
            const int p = tid + 256 * ii;
            const int kp = p / 24, dp = p % 24;
            const int d = 2 * dp;
            sVh[d * VSTR + kp]       = pack_f16(pV[2 * ii].x, pV[2 * ii + 1].x);
            sVh[(d + 1) * VSTR + kp] = pack_f16(pV[2 * ii].y, pV[2 * ii + 1].y);
        }
        if (tid < 192) sC[tid % 3][tid / 3] = pC;
        __syncthreads();

        if (it + 1 < N_ITERS) {
            const int j1 = (it + 1) * TJ;
            #pragma unroll
            for (int ii = 0; ii < 3; ii++) {
                const int idx = tid + 256 * ii;
                const int r = idx / 12, c4 = (idx % 12) * 4;
                pK[ii] = __ldg(reinterpret_cast<const float4*>(gKbase + (size_t)(j1 + r) * QKV_COLS + c4));
            }
            #pragma unroll
            for (int ii = 0; ii < 3; ii++) {
                const int p = tid + 256 * ii;
                const int kp = p / 24, dp = p % 24;
                pV[2 * ii]     = __ldg(reinterpret_cast<const float2*>(gVbase + (size_t)(j1 + 2 * kp) * QKV_COLS + 2 * dp));
                pV[2 * ii + 1] = __ldg(reinterpret_cast<const float2*>(gVbase + (size_t)(j1 + 2 * kp + 1) * QKV_COLS + 2 * dp));
            }
            if (tid < 192) {
                pC = __ldg(coords + (size_t)(b * NTOK + j1 + tid / 3) * 3 + (tid % 3));
            }
        }

        float s[2][8][4];
        #pragma unroll
        for (int mt = 0; mt < 2; mt++)
            #pragma unroll
            for (int nb = 0; nb < 8; nb++)
                #pragma unroll
                for (int e = 0; e < 4; e++) s[mt][nb][e] = 0.f;

        #pragma unroll
        for (int kb = 0; kb < 3; kb++) {
            #pragma unroll
            for (int nbp = 0; nbp < 4; nbp++) {
                const int nb0 = 2 * nbp, nb1 = 2 * nbp + 1;
                const int kb0 = (8 * nb0 + g) * KSTR + 8 * kb;
                const int kb1 = (8 * nb1 + g) * KSTR + 8 * kb;
                uint32_t b0h[2], b1h[2];
                b0h[0] = sKh[kb0 + t]; b0h[1] = sKh[kb0 + t + 4];
                b1h[0] = sKh[kb1 + t]; b1h[1] = sKh[kb1 + t + 4];
                mma_f16(s[0][nb0], qh[0][kb], b0h);
                mma_f16(s[0][nb1], qh[0][kb], b1h);
                mma_f16(s[1][nb0], qh[1][kb], b0h);
                mma_f16(s[1][nb1], qh[1][kb], b1h);
            }
        }

        #pragma unroll
        for (int kb = 0; kb < 4; kb++) {
            #pragma unroll
            for (int nbo = 0; nbo < 2; nbo++) {
                const int nb = 2 * kb + nbo;
                const int c0 = 8 * nb + 2 * t;
                const float kx0 = sC[0][c0], ky0 = sC[1][c0], kz0 = sC[2][c0];
                const float kx1 = sC[0][c0 + 1], ky1 = sC[1][c0 + 1], kz1 = sC[2][c0 + 1];
                #pragma unroll
                for (int mt = 0; mt < 2; mt++) {
                    #pragma unroll
                    for (int half = 0; half < 2; half++) {
                        const int rr = 2 * mt + half;
                        float dx0 = qcx[rr] - kx0, dy0 = qcy[rr] - ky0, dz0 = qcz[rr] - kz0;
                        float dx1 = qcx[rr] - kx1, dy1 = qcy[rr] - ky1, dz1 = qcz[rr] - kz1;
                        float d0 = sqrt_approx(fmaf(dx0, dx0, fmaf(dy0, dy0, dz0 * dz0)));
                        float d1 = sqrt_approx(fmaf(dx1, dx1, fmaf(dy1, dy1, dz1 * dz1)));
                        float p0 = ex2_approx(fmaf(wd2, d0, s[mt][nb][2 * half]));
                        float p1 = ex2_approx(fmaf(wd2, d1, s[mt][nb][2 * half + 1]));
                        s[mt][nb][2 * half] = p0;
                        s[mt][nb][2 * half + 1] = p1;
                        lsum[rr] += p0 + p1;
                    }
                }
            }
            uint32_t ah[2][4];
            #pragma unroll
            for (int mt = 0; mt < 2; mt++) {
                ah[mt][0] = pack_f16(s[mt][2 * kb][0],     s[mt][2 * kb][1]);
                ah[mt][1] = pack_f16(s[mt][2 * kb][2],     s[mt][2 * kb][3]);
                ah[mt][2] = pack_f16(s[mt][2 * kb + 1][0], s[mt][2 * kb + 1][1]);
                ah[mt][3] = pack_f16(s[mt][2 * kb + 1][2], s[mt][2 * kb + 1][3]);
            }
            #pragma unroll
            for (int nbp = 0; nbp < 3; nbp++) {
                const int nb0 = 2 * nbp, nb1 = 2 * nbp + 1;
                const int vb0 = (8 * nb0 + g) * VSTR + 8 * kb;
                const int vb1 = (8 * nb1 + g) * VSTR + 8 * kb;
                uint32_t v0h[2], v1h[2];
                v0h[0] = sVh[vb0 + t]; v0h[1] = sVh[vb0 + t + 4];
                v1h[0] = sVh[vb1 + t]; v1h[1] = sVh[vb1 + t + 4];
                mma_f16(o[0][nb0], ah[0], v0h);
                mma_f16(o[0][nb1], ah[0], v1h);
                mma_f16(o[1][nb0], ah[1], v0h);
                mma_f16(o[1][nb1], ah[1], v1h);
            }
        }
    }

    #pragma unroll
    for (int rr = 0; rr < 4; rr++) {
        lsum[rr] += __shfl_xor_sync(0xffffffffu, lsum[rr], 1);
        lsum[rr] += __shfl_xor_sync(0xffffffffu, lsum[rr], 2);
        lsum[rr] = 1.f / lsum[rr];
    }

    // epilogue: fp16 output (single rounding; feeds single-term out-proj)
    #pragma unroll
    for (int mt = 0; mt < 2; mt++) {
        const int rowA = 32 * w + 16 * mt + g;
        const size_t baseA = (size_t)(b * NTOK + q0 + rowA) * D_MODEL + h * HEAD_DIM;
        const size_t baseB = baseA + (size_t)8 * D_MODEL;
        const float invA = lsum[2 * mt], invB = lsum[2 * mt + 1];
        #pragma unroll
        for (int nb = 0; nb < 6; nb++) {
            const int c = 8 * nb + 2 * t;
            *reinterpret_cast<uint32_t*>(oh + baseA + c) =
                pack_f16(o[mt][nb][0] * invA, o[mt][nb][1] * invA);
            *reinterpret_cast<uint32_t*>(oh + baseB + c) =
                pack_f16(o[mt][nb][2] * invB, o[mt][nb][3] * invB);
        }
    }
}

// ---------------------------------------------------------------------------
extern "C" void kernel_launch(void* const* d_in, const int* in_sizes, int n_in,
                              void* d_out, int out_size)
{
    const float* x      = (const float*)d_in[0];
    const float* coords = (const float*)d_in[1];
    const float* W_qkv  = (const float*)d_in[2];
    const float* b_qkv  = (const float*)d_in[3];
    const float* W_dist = (const float*)d_in[4];
    const float* W_out  = (const float*)d_in[6];
    const float* b_out  = (const float*)d_in[7];
    float* out = (float*)d_out;

    __half *xh, *xl, *oh;
    float* qkvf;
    uint32_t *wqt, *wot;
    cudaGetSymbolAddress((void**)&xh, g_xh);
    cudaGetSymbolAddress((void**)&xl, g_xl);
    cudaGetSymbolAddress((void**)&wqt, g_wqt);
    cudaGetSymbolAddress((void**)&wot, g_wot);
    cudaGetSymbolAddress((void**)&qkvf, g_qkv);
    cudaGetSymbolAddress((void**)&oh, g_oh);

    cudaFuncSetAttribute(gemm_h_kernel,
                         cudaFuncAttributeMaxDynamicSharedMemorySize, SMEM_GEMM);

    // 0) merged prep
    prep_kernel<<<(PREP_TOTAL + 255) / 256, 256>>>(x, xh, xl, W_qkv, wqt, W_out, wot);

    // 1) QKV projection -> fp32; q,k cols single-term, v cols 2-term
    {
        dim3 grid(QKV_COLS / GBN, TOTAL_TOK / GBM);
        gemm_h_kernel<<<grid, 256, SMEM_GEMM>>>(xh, xl, wqt, b_qkv, qkvf,
                                                TOTAL_TOK, QKV_COLS, D_MODEL,
                                                2 * D_MODEL);
    }

    // 2) fused attention -> fp16
    {
        dim3 grid(NTOK / MQ, BATCH * N_HEADS);
        attn_mma_kernel<<<grid, 256>>>(qkvf, coords, W_dist, oh);
    }

    // 3) Output projection (single-term) -> fp32
    {
        dim3 grid(D_MODEL / GBN, TOTAL_TOK / GBM);
        gemm_h_kernel<<<grid, 256, SMEM_GEMM>>>(oh, oh, wot, b_out, out,
                                                TOTAL_TOK, D_MODEL, D_MODEL,
                                                D_MODEL + 1);
    }
}